// round 1
// baseline (speedup 1.0000x reference)
#include <cuda_runtime.h>
#include <cuda_fp16.h>
#include <cstdint>

#define B_ 32
#define N_ 128
#define D_ 128
#define H_ 256
#define ROWS_ (B_ * N_)       // 4096
#define STRIDE_ 280           // padded halves per smem row (560B = 35*16, conflict-free ldmatrix)

// ---------------- scratch (device globals; no allocation allowed) ----------------
__device__ float  g_XN[ROWS_ * D_];     // layernormed+masked x
__device__ __half g_XI[ROWS_ * H_];     // receiver projection x@mw1[:D]
__device__ __half g_S [ROWS_ * H_];     // sender projection x@mw1[D:] + mb1
__device__ __half g_WT[D_ * H_];        // mw2 transposed: WT[d][h]
__device__ float  g_AGG[ROWS_ * D_];    // aggregated messages

// ---------------- mma / ldmatrix helpers ----------------
__device__ __forceinline__ uint32_t smem_u32(const void* p) {
    return (uint32_t)__cvta_generic_to_shared(p);
}
__device__ __forceinline__ void ldsm_x4(uint32_t r[4], uint32_t addr) {
    asm volatile("ldmatrix.sync.aligned.m8n8.x4.shared.b16 {%0,%1,%2,%3}, [%4];"
                 : "=r"(r[0]), "=r"(r[1]), "=r"(r[2]), "=r"(r[3]) : "r"(addr));
}
__device__ __forceinline__ void ldsm_x2(uint32_t& r0, uint32_t& r1, uint32_t addr) {
    asm volatile("ldmatrix.sync.aligned.m8n8.x2.shared.b16 {%0,%1}, [%2];"
                 : "=r"(r0), "=r"(r1) : "r"(addr));
}
__device__ __forceinline__ void mma16816(float c[4], const uint32_t a[4], uint32_t b0, uint32_t b1) {
    asm volatile("mma.sync.aligned.m16n8k16.row.col.f32.f16.f16.f32 "
                 "{%0,%1,%2,%3}, {%4,%5,%6,%7}, {%8,%9}, {%0,%1,%2,%3};"
                 : "+f"(c[0]), "+f"(c[1]), "+f"(c[2]), "+f"(c[3])
                 : "r"(a[0]), "r"(a[1]), "r"(a[2]), "r"(a[3]), "r"(b0), "r"(b1));
}

// ---------------- K0: LayerNorm * mask ----------------
__global__ void k0_ln(const float* __restrict__ nodes, const float* __restrict__ mask,
                      const float* __restrict__ gam, const float* __restrict__ bet) {
    int r = blockIdx.x, t = threadIdx.x;
    float v = nodes[(size_t)r * D_ + t];
    float s = v, s2 = v * v;
#pragma unroll
    for (int o = 16; o > 0; o >>= 1) {
        s  += __shfl_xor_sync(0xffffffffu, s,  o);
        s2 += __shfl_xor_sync(0xffffffffu, s2, o);
    }
    __shared__ float ps[4], ps2[4];
    int w = t >> 5;
    if ((t & 31) == 0) { ps[w] = s; ps2[w] = s2; }
    __syncthreads();
    float sum  = ps[0] + ps[1] + ps[2] + ps[3];
    float sum2 = ps2[0] + ps2[1] + ps2[2] + ps2[3];
    float mu  = sum * (1.0f / 128.0f);
    float var = sum2 * (1.0f / 128.0f) - mu * mu;
    float x = (v - mu) * rsqrtf(var + 1e-5f) * gam[t] + bet[t];
    g_XN[(size_t)r * D_ + t] = x * mask[r];
}

// ---------------- Kwt: transpose mw2[H][D] -> WT[d][h] fp16 ----------------
__global__ void kwt(const float* __restrict__ mw2) {
    int idx = blockIdx.x * 256 + threadIdx.x;   // grid 128 -> 32768
    int d = idx >> 8, h = idx & 255;
    g_WT[idx] = __float2half(mw2[(size_t)h * D_ + d]);
}

// ---------------- K1: XI = XN@mw1[:D],  S = XN@mw1[D:] + mb1 (fp16 out) ----------------
__global__ __launch_bounds__(256) void k1_proj(const float* __restrict__ mw1,
                                               const float* __restrict__ mb1) {
    extern __shared__ char sm1[];
    float* xA = (float*)sm1;             // 32 x 128
    float* wT = (float*)(sm1 + 16384);   // 128 x 64
    int tid = threadIdx.x;
    int r0 = blockIdx.x * 32;

    for (int idx = tid; idx < 1024; idx += 256)
        *(float4*)&xA[idx * 4] = *(const float4*)&g_XN[(size_t)r0 * D_ + idx * 4];

    int rr = tid >> 4, cc = tid & 15;
    for (int ct = 0; ct < 8; ct++) {
        __syncthreads();
        int isS = ct >> 2;
        int h0 = (ct & 3) * 64;
        int koff = isS << 7;
        for (int idx = tid; idx < 2048; idx += 256) {
            int k = idx >> 4, c4 = idx & 15;
            *(float4*)&wT[k * 64 + c4 * 4] =
                *(const float4*)&mw1[(size_t)(k + koff) * H_ + h0 + c4 * 4];
        }
        __syncthreads();
        float acc0[4] = {0.f,0.f,0.f,0.f}, acc1[4] = {0.f,0.f,0.f,0.f};
        const float* xr0 = &xA[(rr * 2) * 128];
        const float* xr1 = xr0 + 128;
#pragma unroll 4
        for (int k = 0; k < 128; k++) {
            float a0 = xr0[k], a1 = xr1[k];
            float4 bv = *(float4*)&wT[k * 64 + cc * 4];
            acc0[0] += a0 * bv.x; acc0[1] += a0 * bv.y; acc0[2] += a0 * bv.z; acc0[3] += a0 * bv.w;
            acc1[0] += a1 * bv.x; acc1[1] += a1 * bv.y; acc1[2] += a1 * bv.z; acc1[3] += a1 * bv.w;
        }
        int row0 = r0 + rr * 2;
        int hb = h0 + cc * 4;
        if (!isS) {
#pragma unroll
            for (int p = 0; p < 4; p++) {
                g_XI[(size_t)row0 * H_ + hb + p]       = __float2half(acc0[p]);
                g_XI[(size_t)(row0 + 1) * H_ + hb + p] = __float2half(acc1[p]);
            }
        } else {
#pragma unroll
            for (int p = 0; p < 4; p++) {
                float bb = mb1[hb + p];
                g_S[(size_t)row0 * H_ + hb + p]       = __float2half(acc0[p] + bb);
                g_S[(size_t)(row0 + 1) * H_ + hb + p] = __float2half(acc1[p] + bb);
            }
        }
    }
}

// ---------------- K2: main edge-MLP GEMM + fused relu/mask/j-reduction ----------------
// grid = 512 (b = bx>>4, i0 = (bx&15)*8), 256 threads (8 warps)
// smem: hA[128][280]h  wB[128][280]h  xi[8][256]h  agg[8][128]f  mb2[128]f  maskJ[128]f
#define SM_HA   0
#define SM_WB   71680
#define SM_XI   143360
#define SM_AGG  147456
#define SM_MB2  151552
#define SM_MSK  152064
#define SM_TOT  152576

__global__ __launch_bounds__(256, 1) void k2_main(const float* __restrict__ mb2,
                                                  const float* __restrict__ mask) {
    extern __shared__ char sm[];
    __half* hA   = (__half*)(sm + SM_HA);
    __half* wB   = (__half*)(sm + SM_WB);
    __half* xiS  = (__half*)(sm + SM_XI);
    float*  agg  = (float*)(sm + SM_AGG);
    float*  mb2s = (float*)(sm + SM_MB2);
    float*  mskJ = (float*)(sm + SM_MSK);

    int tid = threadIdx.x;
    int b  = blockIdx.x >> 4;
    int i0 = (blockIdx.x & 15) << 3;

    // load weights (WT[d][h]) into padded smem
    for (int idx = tid; idx < 128 * 32; idx += 256) {
        int d = idx >> 5, c = idx & 31;
        *(uint4*)&wB[d * STRIDE_ + c * 8] = *(const uint4*)&g_WT[d * H_ + c * 8];
    }
    {   // xi rows for this block's 8 i's
        int ii = tid >> 5, c = tid & 31;
        *(uint4*)&xiS[ii * H_ + c * 8] =
            *(const uint4*)&g_XI[((size_t)(b * N_ + i0 + ii)) * H_ + c * 8];
    }
    if (tid < 128) { mb2s[tid] = mb2[tid]; mskJ[tid] = mask[b * N_ + tid]; }
    for (int idx = tid; idx < 1024; idx += 256) agg[idx] = 0.f;

    int lane = tid & 31, w = tid >> 5;
    int wn = w & 1, wm = w >> 1;            // warp tile: 2 m-tiles x 8 n-tiles
    int n0 = wn * 64;
    uint32_t aB0 = smem_u32(&hA[(wm * 32 + (lane & 15)) * STRIDE_ + ((lane >> 4) & 1) * 8]);
    uint32_t aB1 = aB0 + 16 * STRIDE_ * 2;
    uint32_t bB  = smem_u32(&wB[(n0 + (lane & 7)) * STRIDE_ + ((lane >> 3) & 1) * 8]);

    float C[2][8][4] = {};
    const __half2 z2 = __float2half2_rn(0.f);

    for (int jt = 0; jt < 8; jt++) {
        __syncthreads();                    // all warps done reading hA
        int j0 = jt * 16;
        // build h tile: rows r = ii*16+jj, 256 cols, fp16
        for (int e = tid; e < 4096; e += 256) {
            int r = e >> 5, cv = e & 31;
            int ii = r >> 4, jj = r & 15;
            uint4 sv = *(const uint4*)&g_S[((size_t)(b * N_ + j0 + jj)) * H_ + cv * 8];
            uint4 xv = *(const uint4*)&xiS[ii * H_ + cv * 8];
            const __half2* sp = (const __half2*)&sv;
            const __half2* xp = (const __half2*)&xv;
            uint4 ov;
            __half2* op = (__half2*)&ov;
#pragma unroll
            for (int q = 0; q < 4; q++) op[q] = __hmax2(__hadd2(sp[q], xp[q]), z2);
            *(uint4*)&hA[r * STRIDE_ + cv * 8] = ov;
        }
        __syncthreads();

        // K loop: 16 k-steps of 16
#pragma unroll
        for (int kt = 0; kt < 16; kt++) {
            uint32_t a0[4], a1[4];
            ldsm_x4(a0, aB0 + kt * 32);
            ldsm_x4(a1, aB1 + kt * 32);
#pragma unroll
            for (int ni = 0; ni < 8; ni++) {
                uint32_t b0, b1;
                ldsm_x2(b0, b1, bB + ni * (8 * STRIDE_ * 2) + kt * 32);
                mma16816(C[0][ni], a0, b0, b1);
                mma16816(C[1][ni], a1, b0, b1);
            }
        }

        // epilogue: relu(+mb2)*mask_j, reduce over j (rows), accumulate into agg
        float mA = mskJ[j0 + (lane >> 2)];
        float mB = mskJ[j0 + (lane >> 2) + 8];
#pragma unroll
        for (int mi = 0; mi < 2; mi++) {
            int ii = wm * 2 + mi;
#pragma unroll
            for (int ni = 0; ni < 8; ni++) {
                int n = n0 + ni * 8 + (lane & 3) * 2;
                float bn0 = mb2s[n], bn1 = mb2s[n + 1];
                float s0 = fmaxf(C[mi][ni][0] + bn0, 0.f) * mA + fmaxf(C[mi][ni][2] + bn0, 0.f) * mB;
                float s1 = fmaxf(C[mi][ni][1] + bn1, 0.f) * mA + fmaxf(C[mi][ni][3] + bn1, 0.f) * mB;
                C[mi][ni][0] = C[mi][ni][1] = C[mi][ni][2] = C[mi][ni][3] = 0.f;
#pragma unroll
                for (int o = 4; o < 32; o <<= 1) {
                    s0 += __shfl_xor_sync(0xffffffffu, s0, o);
                    s1 += __shfl_xor_sync(0xffffffffu, s1, o);
                }
                if (lane < 4) {
                    agg[ii * 128 + n]     += s0;
                    agg[ii * 128 + n + 1] += s1;
                }
            }
        }
    }
    __syncthreads();
    for (int idx = tid; idx < 1024; idx += 256) {
        int ii = idx >> 7, d = idx & 127;
        g_AGG[((size_t)(b * N_ + i0 + ii)) * D_ + d] = agg[idx];
    }
}

// ---------------- K3: update MLP + residual + mask ----------------
__global__ __launch_bounds__(256) void k3_final(
    const float* __restrict__ nodes, const float* __restrict__ mask,
    const float* __restrict__ uw1, const float* __restrict__ ub1,
    const float* __restrict__ uw2, const float* __restrict__ ub2,
    float* __restrict__ out) {
    extern __shared__ char sm3[];
    float* sN = (float*)sm3;              // 32x128
    float* sA = (float*)(sm3 + 16384);    // 32x128
    float* sU = (float*)(sm3 + 32768);    // 32x256
    float* wb = (float*)(sm3 + 65536);    // up to 16384 floats
    int tid = threadIdx.x;
    int r0 = blockIdx.x * 32;

    for (int idx = tid; idx < 1024; idx += 256) {
        *(float4*)&sN[idx * 4] = *(const float4*)&nodes[(size_t)r0 * D_ + idx * 4];
        *(float4*)&sA[idx * 4] = *(const float4*)&g_AGG[(size_t)r0 * D_ + idx * 4];
    }
    int rr = tid >> 4, cc = tid & 15;
    float* w1a = wb;
    float* w1b = wb + 8192;
    for (int ct = 0; ct < 4; ct++) {
        __syncthreads();
        int h0 = ct * 64;
        for (int idx = tid; idx < 2048; idx += 256) {
            int k = idx >> 4, c4 = idx & 15;
            *(float4*)&w1a[k * 64 + c4 * 4] = *(const float4*)&uw1[(size_t)k * H_ + h0 + c4 * 4];
            *(float4*)&w1b[k * 64 + c4 * 4] = *(const float4*)&uw1[(size_t)(k + 128) * H_ + h0 + c4 * 4];
        }
        __syncthreads();
        float acc0[4] = {0.f,0.f,0.f,0.f}, acc1[4] = {0.f,0.f,0.f,0.f};
        const float* nr0 = &sN[rr * 2 * 128]; const float* nr1 = nr0 + 128;
        const float* ar0 = &sA[rr * 2 * 128]; const float* ar1 = ar0 + 128;
#pragma unroll 2
        for (int k = 0; k < 128; k++) {
            float a0 = nr0[k], a1 = nr1[k], q0 = ar0[k], q1 = ar1[k];
            float4 b1v = *(float4*)&w1a[k * 64 + cc * 4];
            float4 b2v = *(float4*)&w1b[k * 64 + cc * 4];
            acc0[0] += a0 * b1v.x + q0 * b2v.x;  acc0[1] += a0 * b1v.y + q0 * b2v.y;
            acc0[2] += a0 * b1v.z + q0 * b2v.z;  acc0[3] += a0 * b1v.w + q0 * b2v.w;
            acc1[0] += a1 * b1v.x + q1 * b2v.x;  acc1[1] += a1 * b1v.y + q1 * b2v.y;
            acc1[2] += a1 * b1v.z + q1 * b2v.z;  acc1[3] += a1 * b1v.w + q1 * b2v.w;
        }
        int hb = h0 + cc * 4;
#pragma unroll
        for (int p = 0; p < 4; p++) {
            sU[(rr * 2) * 256 + hb + p]     = fmaxf(acc0[p] + ub1[hb + p], 0.f);
            sU[(rr * 2 + 1) * 256 + hb + p] = fmaxf(acc1[p] + ub1[hb + p], 0.f);
        }
    }
    __syncthreads();
    for (int ct = 0; ct < 2; ct++) {
        __syncthreads();
        int c0 = ct * 64;
        for (int idx = tid; idx < 4096; idx += 256) {
            int k = idx >> 4, c4 = idx & 15;
            *(float4*)&wb[k * 64 + c4 * 4] = *(const float4*)&uw2[(size_t)k * D_ + c0 + c4 * 4];
        }
        __syncthreads();
        float acc0[4] = {0.f,0.f,0.f,0.f}, acc1[4] = {0.f,0.f,0.f,0.f};
        const float* ur0 = &sU[rr * 2 * 256]; const float* ur1 = ur0 + 256;
#pragma unroll 2
        for (int k = 0; k < 256; k++) {
            float a0 = ur0[k], a1 = ur1[k];
            float4 bv = *(float4*)&wb[k * 64 + cc * 4];
            acc0[0] += a0 * bv.x; acc0[1] += a0 * bv.y; acc0[2] += a0 * bv.z; acc0[3] += a0 * bv.w;
            acc1[0] += a1 * bv.x; acc1[1] += a1 * bv.y; acc1[2] += a1 * bv.z; acc1[3] += a1 * bv.w;
        }
        int row0 = r0 + rr * 2;
        int cb = c0 + cc * 4;
        float m0 = mask[row0], m1 = mask[row0 + 1];
#pragma unroll
        for (int p = 0; p < 4; p++) {
            out[(size_t)row0 * D_ + cb + p] =
                (sN[(rr * 2) * 128 + cb + p] + acc0[p] + ub2[cb + p]) * m0;
            out[(size_t)(row0 + 1) * D_ + cb + p] =
                (sN[(rr * 2 + 1) * 128 + cb + p] + acc1[p] + ub2[cb + p]) * m1;
        }
    }
}

// ---------------- launch ----------------
extern "C" void kernel_launch(void* const* d_in, const int* in_sizes, int n_in,
                              void* d_out, int out_size) {
    const float* nodes = (const float*)d_in[0];
    const float* mask  = (const float*)d_in[1];
    const float* ln_g  = (const float*)d_in[2];
    const float* ln_b  = (const float*)d_in[3];
    const float* mw1   = (const float*)d_in[4];
    const float* mb1   = (const float*)d_in[5];
    const float* mw2   = (const float*)d_in[6];
    const float* mb2   = (const float*)d_in[7];
    const float* uw1   = (const float*)d_in[8];
    const float* ub1   = (const float*)d_in[9];
    const float* uw2   = (const float*)d_in[10];
    const float* ub2   = (const float*)d_in[11];
    float* out = (float*)d_out;

    cudaFuncSetAttribute(k1_proj,  cudaFuncAttributeMaxDynamicSharedMemorySize, 49152);
    cudaFuncSetAttribute(k2_main,  cudaFuncAttributeMaxDynamicSharedMemorySize, SM_TOT);
    cudaFuncSetAttribute(k3_final, cudaFuncAttributeMaxDynamicSharedMemorySize, 131072);

    k0_ln<<<ROWS_, 128>>>(nodes, mask, ln_g, ln_b);
    kwt<<<128, 256>>>(mw2);
    k1_proj<<<128, 256, 49152>>>(mw1, mb1);
    k2_main<<<512, 256, SM_TOT>>>(mb2, mask);
    k3_final<<<128, 256, 131072>>>(nodes, mask, uw1, ub1, uw2, ub2, out);
}

// round 2
// speedup vs baseline: 1.1512x; 1.1512x over previous
#include <cuda_runtime.h>
#include <cuda_fp16.h>
#include <cstdint>

#define B_ 32
#define N_ 128
#define D_ 128
#define H_ 256
#define ROWS_ (B_ * N_)       // 4096
#define ST_ 264               // padded halves per smem row (528B = 33*16, mod128=16 -> conflict-free ldmatrix)

// ---------------- scratch (device globals; no allocation allowed) ----------------
__device__ __half g_XI[ROWS_ * H_];     // receiver projection x@mw1[:D]
__device__ __half g_S [ROWS_ * H_];     // sender projection x@mw1[D:] + mb1
__device__ __half g_WT[D_ * H_];        // mw2 transposed: WT[d][h]
__device__ float  g_AGG[ROWS_ * D_];    // aggregated messages

// ---------------- mma / ldmatrix helpers ----------------
__device__ __forceinline__ uint32_t smem_u32(const void* p) {
    return (uint32_t)__cvta_generic_to_shared(p);
}
__device__ __forceinline__ void ldsm_x4(uint32_t r[4], uint32_t addr) {
    asm volatile("ldmatrix.sync.aligned.m8n8.x4.shared.b16 {%0,%1,%2,%3}, [%4];"
                 : "=r"(r[0]), "=r"(r[1]), "=r"(r[2]), "=r"(r[3]) : "r"(addr));
}
__device__ __forceinline__ void mma16816(float c[4], const uint32_t a[4], uint32_t b0, uint32_t b1) {
    asm volatile("mma.sync.aligned.m16n8k16.row.col.f32.f16.f16.f32 "
                 "{%0,%1,%2,%3}, {%4,%5,%6,%7}, {%8,%9}, {%0,%1,%2,%3};"
                 : "+f"(c[0]), "+f"(c[1]), "+f"(c[2]), "+f"(c[3])
                 : "r"(a[0]), "r"(a[1]), "r"(a[2]), "r"(a[3]), "r"(b0), "r"(b1));
}

// ---------------- Kwt: transpose mw2[H][D] -> WT[d][h] fp16 ----------------
__global__ void kwt(const float* __restrict__ mw2) {
    int idx = blockIdx.x * 256 + threadIdx.x;   // grid 128 -> 32768
    int d = idx >> 8, h = idx & 255;
    g_WT[idx] = __float2half(mw2[(size_t)h * D_ + d]);
}

// ---------------- K1: fused LayerNorm + projections  XI = XN@mw1[:D], S = XN@mw1[D:] + mb1 ----------------
__global__ __launch_bounds__(256) void k1_proj(const float* __restrict__ nodes,
                                               const float* __restrict__ mask,
                                               const float* __restrict__ gam,
                                               const float* __restrict__ bet,
                                               const float* __restrict__ mw1,
                                               const float* __restrict__ mb1) {
    extern __shared__ char sm1[];
    float* xA = (float*)sm1;             // 32 x 128
    float* wT = (float*)(sm1 + 16384);   // 128 x 64
    int tid = threadIdx.x;
    int r0 = blockIdx.x * 32;

    // fused LayerNorm * mask -> xA
    {
        int row = tid >> 3, p = tid & 7;        // 8 threads per row, 16 elems each
        const float* np = &nodes[(size_t)(r0 + row) * D_ + p * 16];
        float4 v[4];
#pragma unroll
        for (int q = 0; q < 4; q++) v[q] = *(const float4*)&np[q * 4];
        float s = 0.f, s2 = 0.f;
#pragma unroll
        for (int q = 0; q < 4; q++) {
            s  += v[q].x + v[q].y + v[q].z + v[q].w;
            s2 += v[q].x*v[q].x + v[q].y*v[q].y + v[q].z*v[q].z + v[q].w*v[q].w;
        }
#pragma unroll
        for (int o = 1; o < 8; o <<= 1) {
            s  += __shfl_xor_sync(0xffffffffu, s,  o);
            s2 += __shfl_xor_sync(0xffffffffu, s2, o);
        }
        float mu  = s * (1.0f / 128.0f);
        float var = s2 * (1.0f / 128.0f) - mu * mu;
        float rs  = rsqrtf(var + 1e-5f);
        float m   = mask[r0 + row];
        float* xo = &xA[row * 128 + p * 16];
        const float* gp = &gam[p * 16];
        const float* bp = &bet[p * 16];
#pragma unroll
        for (int q = 0; q < 4; q++) {
            xo[q*4+0] = ((v[q].x - mu) * rs * gp[q*4+0] + bp[q*4+0]) * m;
            xo[q*4+1] = ((v[q].y - mu) * rs * gp[q*4+1] + bp[q*4+1]) * m;
            xo[q*4+2] = ((v[q].z - mu) * rs * gp[q*4+2] + bp[q*4+2]) * m;
            xo[q*4+3] = ((v[q].w - mu) * rs * gp[q*4+3] + bp[q*4+3]) * m;
        }
    }

    int rr = tid >> 4, cc = tid & 15;
    for (int ct = 0; ct < 8; ct++) {
        __syncthreads();
        int isS = ct >> 2;
        int h0 = (ct & 3) * 64;
        int koff = isS << 7;
        for (int idx = tid; idx < 2048; idx += 256) {
            int k = idx >> 4, c4 = idx & 15;
            *(float4*)&wT[k * 64 + c4 * 4] =
                *(const float4*)&mw1[(size_t)(k + koff) * H_ + h0 + c4 * 4];
        }
        __syncthreads();
        float acc0[4] = {0.f,0.f,0.f,0.f}, acc1[4] = {0.f,0.f,0.f,0.f};
        const float* xr0 = &xA[(rr * 2) * 128];
        const float* xr1 = xr0 + 128;
#pragma unroll 4
        for (int k = 0; k < 128; k++) {
            float a0 = xr0[k], a1 = xr1[k];
            float4 bv = *(float4*)&wT[k * 64 + cc * 4];
            acc0[0] += a0 * bv.x; acc0[1] += a0 * bv.y; acc0[2] += a0 * bv.z; acc0[3] += a0 * bv.w;
            acc1[0] += a1 * bv.x; acc1[1] += a1 * bv.y; acc1[2] += a1 * bv.z; acc1[3] += a1 * bv.w;
        }
        int row0 = r0 + rr * 2;
        int hb = h0 + cc * 4;
        if (!isS) {
#pragma unroll
            for (int p = 0; p < 4; p++) {
                g_XI[(size_t)row0 * H_ + hb + p]       = __float2half(acc0[p]);
                g_XI[(size_t)(row0 + 1) * H_ + hb + p] = __float2half(acc1[p]);
            }
        } else {
#pragma unroll
            for (int p = 0; p < 4; p++) {
                float bb = mb1[hb + p];
                g_S[(size_t)row0 * H_ + hb + p]       = __float2half(acc0[p] + bb);
                g_S[(size_t)(row0 + 1) * H_ + hb + p] = __float2half(acc1[p] + bb);
            }
        }
    }
}

// ---------------- K2: edge-MLP GEMM, A-fragments built in registers ----------------
// grid = 128 (b = bx>>2, ibase = (bx&3)*32), 256 threads = 8 warps:
// 4 m-groups (j, 32 rows each) x 2 n-groups (D, 64 cols each); 16 ip iters of 2 i's.
#define SM_S   0                         // 128 x 264 half  (s rows, this b)
#define SM_W   67584                     // 128 x 264 half  (WT rows d, cols h)
#define SM_X   135168                    // 32 x 256 half   (xi rows for this i-chunk)
#define SM_P   151552                    // part[4][2][128] float
#define SM_B2  155648                    // mb2 128 float
#define SM_MK  156160                    // maskJ 128 float
#define SM_TOT 156672

__global__ __launch_bounds__(256, 1) void k2_main(const float* __restrict__ mb2,
                                                  const float* __restrict__ mask) {
    extern __shared__ char sm[];
    __half* sS   = (__half*)(sm + SM_S);
    __half* wB   = (__half*)(sm + SM_W);
    __half* xiS  = (__half*)(sm + SM_X);
    float*  part = (float*)(sm + SM_P);
    float*  mb2s = (float*)(sm + SM_B2);
    float*  mskJ = (float*)(sm + SM_MK);

    int tid = threadIdx.x;
    int b     = blockIdx.x >> 2;
    int ibase = (blockIdx.x & 3) << 5;

    for (int idx = tid; idx < 4096; idx += 256) {
        int r = idx >> 5, c = idx & 31;
        *(uint4*)&sS[r * ST_ + c * 8] = *(const uint4*)&g_S[((size_t)(b * N_ + r)) * H_ + c * 8];
        *(uint4*)&wB[r * ST_ + c * 8] = *(const uint4*)&g_WT[r * H_ + c * 8];
    }
    for (int idx = tid; idx < 1024; idx += 256) {
        int r = idx >> 5, c = idx & 31;
        *(uint4*)&xiS[r * 256 + c * 8] =
            *(const uint4*)&g_XI[((size_t)(b * N_ + ibase + r)) * H_ + c * 8];
    }
    if (tid < 128) { mb2s[tid] = mb2[tid]; mskJ[tid] = mask[b * N_ + tid]; }
    __syncthreads();

    int lane = tid & 31, w = tid >> 5;
    int mg = w >> 1, ng = w & 1;
    uint32_t aB = smem_u32(&sS[(mg * 32 + (lane & 15)) * ST_ + ((lane >> 4) & 1) * 8]);
    uint32_t bB = smem_u32(&wB[(ng * 64 + (lane & 15)) * ST_ + ((lane >> 4) & 1) * 8]);

    const __half2 z2 = __float2half2_rn(0.f);
    float mrow[2][2];
#pragma unroll
    for (int mt = 0; mt < 2; mt++) {
        mrow[mt][0] = mskJ[mg * 32 + mt * 16 + (lane >> 2)];
        mrow[mt][1] = mskJ[mg * 32 + mt * 16 + (lane >> 2) + 8];
    }

    for (int ip = 0; ip < 16; ip++) {
        float C[2][2][8][4] = {};            // [il][mt][nt][4]
        int i0 = ip * 2;

#pragma unroll 4
        for (int kt = 0; kt < 16; kt++) {
            uint32_t bf[4][4];
#pragma unroll
            for (int q = 0; q < 4; q++)
                ldsm_x4(bf[q], bB + q * (16 * ST_ * 2) + kt * 32);
            __half2 xA[2], xB[2];
#pragma unroll
            for (int il = 0; il < 2; il++) {
                const __half2* xp = (const __half2*)&xiS[(i0 + il) * 256 + kt * 16 + (lane & 3) * 2];
                xA[il] = xp[0];
                xB[il] = xp[4];
            }
#pragma unroll
            for (int mt = 0; mt < 2; mt++) {
                uint32_t sf[4];
                ldsm_x4(sf, aB + mt * (16 * ST_ * 2) + kt * 32);
#pragma unroll
                for (int il = 0; il < 2; il++) {
                    uint32_t a[4];
                    __half2 t;
                    t = __hmax2(__hadd2(*(__half2*)&sf[0], xA[il]), z2); a[0] = *(uint32_t*)&t;
                    t = __hmax2(__hadd2(*(__half2*)&sf[1], xA[il]), z2); a[1] = *(uint32_t*)&t;
                    t = __hmax2(__hadd2(*(__half2*)&sf[2], xB[il]), z2); a[2] = *(uint32_t*)&t;
                    t = __hmax2(__hadd2(*(__half2*)&sf[3], xB[il]), z2); a[3] = *(uint32_t*)&t;
#pragma unroll
                    for (int q = 0; q < 4; q++) {
                        mma16816(C[il][mt][q * 2],     a, bf[q][0], bf[q][2]);
                        mma16816(C[il][mt][q * 2 + 1], a, bf[q][1], bf[q][3]);
                    }
                }
            }
        }

        // epilogue: relu(+mb2)*mask_j, reduce rows (j) -> part, combine m-groups
#pragma unroll
        for (int il = 0; il < 2; il++) {
#pragma unroll
            for (int nt = 0; nt < 8; nt++) {
                int n = ng * 64 + (nt >> 1) * 16 + (nt & 1) * 8 + (lane & 3) * 2;
                float bn0 = mb2s[n], bn1 = mb2s[n + 1];
                float s0 = 0.f, s1 = 0.f;
#pragma unroll
                for (int mt = 0; mt < 2; mt++) {
                    s0 += fmaxf(C[il][mt][nt][0] + bn0, 0.f) * mrow[mt][0]
                        + fmaxf(C[il][mt][nt][2] + bn0, 0.f) * mrow[mt][1];
                    s1 += fmaxf(C[il][mt][nt][1] + bn1, 0.f) * mrow[mt][0]
                        + fmaxf(C[il][mt][nt][3] + bn1, 0.f) * mrow[mt][1];
                }
#pragma unroll
                for (int o = 4; o < 32; o <<= 1) {
                    s0 += __shfl_xor_sync(0xffffffffu, s0, o);
                    s1 += __shfl_xor_sync(0xffffffffu, s1, o);
                }
                if (lane < 4) {
                    part[(mg * 2 + il) * 128 + n]     = s0;
                    part[(mg * 2 + il) * 128 + n + 1] = s1;
                }
            }
        }
        __syncthreads();
        {
            int il = tid >> 7, c = tid & 127;
            float v = part[il * 128 + c] + part[(2 + il) * 128 + c]
                    + part[(4 + il) * 128 + c] + part[(6 + il) * 128 + c];
            g_AGG[((size_t)(b * N_ + ibase + i0 + il)) * D_ + c] = v;
        }
        __syncthreads();
    }
}

// ---------------- K3: update MLP + residual + mask ----------------
__global__ __launch_bounds__(256) void k3_final(
    const float* __restrict__ nodes, const float* __restrict__ mask,
    const float* __restrict__ uw1, const float* __restrict__ ub1,
    const float* __restrict__ uw2, const float* __restrict__ ub2,
    float* __restrict__ out) {
    extern __shared__ char sm3[];
    float* sN = (float*)sm3;              // 32x128
    float* sA = (float*)(sm3 + 16384);    // 32x128
    float* sU = (float*)(sm3 + 32768);    // 32x256
    float* wb = (float*)(sm3 + 65536);    // up to 16384 floats
    int tid = threadIdx.x;
    int r0 = blockIdx.x * 32;

    for (int idx = tid; idx < 1024; idx += 256) {
        *(float4*)&sN[idx * 4] = *(const float4*)&nodes[(size_t)r0 * D_ + idx * 4];
        *(float4*)&sA[idx * 4] = *(const float4*)&g_AGG[(size_t)r0 * D_ + idx * 4];
    }
    int rr = tid >> 4, cc = tid & 15;
    float* w1a = wb;
    float* w1b = wb + 8192;
    for (int ct = 0; ct < 4; ct++) {
        __syncthreads();
        int h0 = ct * 64;
        for (int idx = tid; idx < 2048; idx += 256) {
            int k = idx >> 4, c4 = idx & 15;
            *(float4*)&w1a[k * 64 + c4 * 4] = *(const float4*)&uw1[(size_t)k * H_ + h0 + c4 * 4];
            *(float4*)&w1b[k * 64 + c4 * 4] = *(const float4*)&uw1[(size_t)(k + 128) * H_ + h0 + c4 * 4];
        }
        __syncthreads();
        float acc0[4] = {0.f,0.f,0.f,0.f}, acc1[4] = {0.f,0.f,0.f,0.f};
        const float* nr0 = &sN[rr * 2 * 128]; const float* nr1 = nr0 + 128;
        const float* ar0 = &sA[rr * 2 * 128]; const float* ar1 = ar0 + 128;
#pragma unroll 2
        for (int k = 0; k < 128; k++) {
            float a0 = nr0[k], a1 = nr1[k], q0 = ar0[k], q1 = ar1[k];
            float4 b1v = *(float4*)&w1a[k * 64 + cc * 4];
            float4 b2v = *(float4*)&w1b[k * 64 + cc * 4];
            acc0[0] += a0 * b1v.x + q0 * b2v.x;  acc0[1] += a0 * b1v.y + q0 * b2v.y;
            acc0[2] += a0 * b1v.z + q0 * b2v.z;  acc0[3] += a0 * b1v.w + q0 * b2v.w;
            acc1[0] += a1 * b1v.x + q1 * b2v.x;  acc1[1] += a1 * b1v.y + q1 * b2v.y;
            acc1[2] += a1 * b1v.z + q1 * b2v.z;  acc1[3] += a1 * b1v.w + q1 * b2v.w;
        }
        int hb = h0 + cc * 4;
#pragma unroll
        for (int p = 0; p < 4; p++) {
            sU[(rr * 2) * 256 + hb + p]     = fmaxf(acc0[p] + ub1[hb + p], 0.f);
            sU[(rr * 2 + 1) * 256 + hb + p] = fmaxf(acc1[p] + ub1[hb + p], 0.f);
        }
    }
    __syncthreads();
    for (int ct = 0; ct < 2; ct++) {
        __syncthreads();
        int c0 = ct * 64;
        for (int idx = tid; idx < 4096; idx += 256) {
            int k = idx >> 4, c4 = idx & 15;
            *(float4*)&wb[k * 64 + c4 * 4] = *(const float4*)&uw2[(size_t)k * D_ + c0 + c4 * 4];
        }
        __syncthreads();
        float acc0[4] = {0.f,0.f,0.f,0.f}, acc1[4] = {0.f,0.f,0.f,0.f};
        const float* ur0 = &sU[rr * 2 * 256]; const float* ur1 = ur0 + 256;
#pragma unroll 2
        for (int k = 0; k < 256; k++) {
            float a0 = ur0[k], a1 = ur1[k];
            float4 bv = *(float4*)&wb[k * 64 + cc * 4];
            acc0[0] += a0 * bv.x; acc0[1] += a0 * bv.y; acc0[2] += a0 * bv.z; acc0[3] += a0 * bv.w;
            acc1[0] += a1 * bv.x; acc1[1] += a1 * bv.y; acc1[2] += a1 * bv.z; acc1[3] += a1 * bv.w;
        }
        int row0 = r0 + rr * 2;
        int cb = c0 + cc * 4;
        float m0 = mask[row0], m1 = mask[row0 + 1];
#pragma unroll
        for (int p = 0; p < 4; p++) {
            out[(size_t)row0 * D_ + cb + p] =
                (sN[(rr * 2) * 128 + cb + p] + acc0[p] + ub2[cb + p]) * m0;
            out[(size_t)(row0 + 1) * D_ + cb + p] =
                (sN[(rr * 2 + 1) * 128 + cb + p] + acc1[p] + ub2[cb + p]) * m1;
        }
    }
}

// ---------------- launch ----------------
extern "C" void kernel_launch(void* const* d_in, const int* in_sizes, int n_in,
                              void* d_out, int out_size) {
    const float* nodes = (const float*)d_in[0];
    const float* mask  = (const float*)d_in[1];
    const float* ln_g  = (const float*)d_in[2];
    const float* ln_b  = (const float*)d_in[3];
    const float* mw1   = (const float*)d_in[4];
    const float* mb1   = (const float*)d_in[5];
    const float* mw2   = (const float*)d_in[6];
    const float* mb2   = (const float*)d_in[7];
    const float* uw1   = (const float*)d_in[8];
    const float* ub1   = (const float*)d_in[9];
    const float* uw2   = (const float*)d_in[10];
    const float* ub2   = (const float*)d_in[11];
    float* out = (float*)d_out;

    cudaFuncSetAttribute(k1_proj,  cudaFuncAttributeMaxDynamicSharedMemorySize, 49152);
    cudaFuncSetAttribute(k2_main,  cudaFuncAttributeMaxDynamicSharedMemorySize, SM_TOT);
    cudaFuncSetAttribute(k3_final, cudaFuncAttributeMaxDynamicSharedMemorySize, 131072);

    kwt<<<128, 256>>>(mw2);
    k1_proj<<<128, 256, 49152>>>(nodes, mask, ln_g, ln_b, mw1, mb1);
    k2_main<<<128, 256, SM_TOT>>>(mb2, mask);
    k3_final<<<128, 256, 131072>>>(nodes, mask, uw1, ub1, uw2, ub2, out);
}

// round 3
// speedup vs baseline: 1.6898x; 1.4679x over previous
#include <cuda_runtime.h>
#include <cuda_fp16.h>
#include <cstdint>

#define B_ 32
#define N_ 128
#define D_ 128
#define H_ 256
#define ROWS_ (B_ * N_)       // 4096
#define ST_ 264               // stride (halves) for K=256 tiles: 528B, mod128=16 -> conflict-free
#define ST1 136               // stride (halves) for K=128 tiles: 272B, mod128=16 -> conflict-free

// ---------------- scratch (device globals; no allocation allowed) ----------------
__device__ __half g_XI[ROWS_ * H_];      // receiver projection x@mw1[:D]
__device__ __half g_S [ROWS_ * H_];      // sender projection x@mw1[D:] + mb1
__device__ __half g_WT [D_ * H_];        // mw2^T: [d][h]
__device__ __half g_W1Ta[H_ * D_];       // mw1[:D]^T:  [h][k] k<128
__device__ __half g_W1Tb[H_ * D_];       // mw1[D:]^T:  [h][k]
__device__ __half g_U1T[H_ * 2 * D_];    // uw1^T: [h][k] k=256 (0:128 nodes, 128:256 agg)
__device__ __half g_U2T[D_ * H_];        // uw2^T: [d][k] k=256
__device__ __half g_NH [ROWS_ * D_];     // nodes fp16
__device__ __half g_AGGH[ROWS_ * D_];    // aggregated messages fp16

// ---------------- mma / ldmatrix helpers ----------------
__device__ __forceinline__ uint32_t smem_u32(const void* p) {
    return (uint32_t)__cvta_generic_to_shared(p);
}
__device__ __forceinline__ void ldsm_x4(uint32_t r[4], uint32_t addr) {
    asm volatile("ldmatrix.sync.aligned.m8n8.x4.shared.b16 {%0,%1,%2,%3}, [%4];"
                 : "=r"(r[0]), "=r"(r[1]), "=r"(r[2]), "=r"(r[3]) : "r"(addr));
}
__device__ __forceinline__ void mma16816(float c[4], const uint32_t a[4], uint32_t b0, uint32_t b1) {
    asm volatile("mma.sync.aligned.m16n8k16.row.col.f32.f16.f16.f32 "
                 "{%0,%1,%2,%3}, {%4,%5,%6,%7}, {%8,%9}, {%0,%1,%2,%3};"
                 : "+f"(c[0]), "+f"(c[1]), "+f"(c[2]), "+f"(c[3])
                 : "r"(a[0]), "r"(a[1]), "r"(a[2]), "r"(a[3]), "r"(b0), "r"(b1));
}

// ---------------- KW: all weight transposes to fp16 + nodes->fp16 ----------------
__global__ void kw(const float* __restrict__ nodes, const float* __restrict__ mw1,
                   const float* __restrict__ mw2, const float* __restrict__ uw1,
                   const float* __restrict__ uw2) {
    int idx = blockIdx.x * 256 + threadIdx.x;
    if (idx < 524288) { g_NH[idx] = __float2half(nodes[idx]); return; }
    idx -= 524288;
    if (idx < 32768) {               // g_W1Ta[h*128+k] = mw1[k][h]
        int h = idx >> 7, k = idx & 127;
        g_W1Ta[idx] = __float2half(mw1[(size_t)k * H_ + h]);
        return;
    }
    idx -= 32768;
    if (idx < 32768) {               // g_W1Tb[h*128+k] = mw1[k+128][h]
        int h = idx >> 7, k = idx & 127;
        g_W1Tb[idx] = __float2half(mw1[(size_t)(k + 128) * H_ + h]);
        return;
    }
    idx -= 32768;
    if (idx < 32768) {               // g_WT[d*256+h] = mw2[h][d]
        int d = idx >> 8, h = idx & 255;
        g_WT[idx] = __float2half(mw2[(size_t)h * D_ + d]);
        return;
    }
    idx -= 32768;
    if (idx < 65536) {               // g_U1T[h*256+k] = uw1[k][h]
        int h = idx >> 8, k = idx & 255;
        g_U1T[idx] = __float2half(uw1[(size_t)k * H_ + h]);
        return;
    }
    idx -= 65536;
    if (idx < 32768) {               // g_U2T[d*256+k] = uw2[k][d]
        int d = idx >> 8, k = idx & 255;
        g_U2T[idx] = __float2half(uw2[(size_t)k * D_ + d]);
    }
}

// ---------------- K1: fused LayerNorm + mma projections ----------------
// grid 128 x 32 rows. warps 0-3: XI (B = W1Ta), warps 4-7: S (B = W1Tb, +mb1)
#define K1_XH 0                      // 32 x 136 half   (8704 B)
#define K1_BA 8704                   // 256 x 136 half  (69632 B)
#define K1_BB 78336                  // 256 x 136 half
#define K1_TOT 147968
__global__ __launch_bounds__(256) void k1_proj(const float* __restrict__ nodes,
                                               const float* __restrict__ mask,
                                               const float* __restrict__ gam,
                                               const float* __restrict__ bet,
                                               const float* __restrict__ mb1) {
    extern __shared__ char sm1[];
    __half* xh = (__half*)(sm1 + K1_XH);
    __half* Ba = (__half*)(sm1 + K1_BA);
    __half* Bb = (__half*)(sm1 + K1_BB);
    int tid = threadIdx.x;
    int r0 = blockIdx.x * 32;

    // load both weight halves into padded smem
    for (int idx = tid; idx < 4096; idx += 256) {
        int r = idx >> 4, c = idx & 15;
        *(uint4*)&Ba[r * ST1 + c * 8] = *(const uint4*)&g_W1Ta[r * 128 + c * 8];
        *(uint4*)&Bb[r * ST1 + c * 8] = *(const uint4*)&g_W1Tb[r * 128 + c * 8];
    }

    // fused LayerNorm * mask -> xh (fp16)
    {
        int row = tid >> 3, p = tid & 7;
        const float* np = &nodes[(size_t)(r0 + row) * D_ + p * 16];
        float4 v[4];
#pragma unroll
        for (int q = 0; q < 4; q++) v[q] = *(const float4*)&np[q * 4];
        float s = 0.f, s2 = 0.f;
#pragma unroll
        for (int q = 0; q < 4; q++) {
            s  += v[q].x + v[q].y + v[q].z + v[q].w;
            s2 += v[q].x*v[q].x + v[q].y*v[q].y + v[q].z*v[q].z + v[q].w*v[q].w;
        }
#pragma unroll
        for (int o = 1; o < 8; o <<= 1) {
            s  += __shfl_xor_sync(0xffffffffu, s,  o);
            s2 += __shfl_xor_sync(0xffffffffu, s2, o);
        }
        float mu  = s * (1.0f / 128.0f);
        float var = s2 * (1.0f / 128.0f) - mu * mu;
        float rs  = rsqrtf(var + 1e-5f);
        float m   = mask[r0 + row];
        __half* xo = &xh[row * ST1 + p * 16];
        const float* gp = &gam[p * 16];
        const float* bp = &bet[p * 16];
        const float* vv = (const float*)v;
#pragma unroll
        for (int q = 0; q < 16; q++)
            xo[q] = __float2half(((vv[q] - mu) * rs * gp[q] + bp[q]) * m);
    }
    __syncthreads();

    int lane = tid & 31, w = tid >> 5;
    int isS = w >> 2, nq = w & 3, n0 = nq * 64;
    const __half* Bsel = isS ? Bb : Ba;
    uint32_t aB = smem_u32(&xh[(lane & 15) * ST1 + ((lane >> 4) & 1) * 8]);
    uint32_t bB = smem_u32(&Bsel[(n0 + (lane & 15)) * ST1 + ((lane >> 4) & 1) * 8]);

    float C[2][8][4] = {};
#pragma unroll
    for (int kt = 0; kt < 8; kt++) {
        uint32_t am[2][4], bf[4][4];
#pragma unroll
        for (int mt = 0; mt < 2; mt++) ldsm_x4(am[mt], aB + mt * (16 * ST1 * 2) + kt * 32);
#pragma unroll
        for (int q = 0; q < 4; q++) ldsm_x4(bf[q], bB + q * (16 * ST1 * 2) + kt * 32);
#pragma unroll
        for (int mt = 0; mt < 2; mt++)
#pragma unroll
            for (int q = 0; q < 4; q++) {
                mma16816(C[mt][q * 2],     am[mt], bf[q][0], bf[q][2]);
                mma16816(C[mt][q * 2 + 1], am[mt], bf[q][1], bf[q][3]);
            }
    }

    __half* dst = isS ? g_S : g_XI;
#pragma unroll
    for (int mt = 0; mt < 2; mt++) {
#pragma unroll
        for (int q = 0; q < 4; q++) {
#pragma unroll
            for (int sub = 0; sub < 2; sub++) {
                int nt = q * 2 + sub;
                int col = n0 + q * 16 + sub * 8 + (lane & 3) * 2;
                float b0 = 0.f, b1 = 0.f;
                if (isS) { b0 = mb1[col]; b1 = mb1[col + 1]; }
                int rowA = r0 + mt * 16 + (lane >> 2);
                __half2 lo = __floats2half2_rn(C[mt][nt][0] + b0, C[mt][nt][1] + b1);
                __half2 hi = __floats2half2_rn(C[mt][nt][2] + b0, C[mt][nt][3] + b1);
                *(__half2*)&dst[(size_t)rowA * H_ + col]       = lo;
                *(__half2*)&dst[(size_t)(rowA + 8) * H_ + col] = hi;
            }
        }
    }
}

// ---------------- K2: edge-MLP GEMM, A-fragments built in registers ----------------
#define SM_S   0                         // 128 x 264 half  (s rows, this b)
#define SM_W   67584                     // 128 x 264 half  (WT rows d, cols h)
#define SM_X   135168                    // 32 x 256 half   (xi rows for this i-chunk)
#define SM_P   151552                    // part[4][2][128] float
#define SM_B2  155648                    // mb2 128 float
#define SM_MK  156160                    // maskJ 128 float
#define SM_TOT 156672

__global__ __launch_bounds__(256, 1) void k2_main(const float* __restrict__ mb2,
                                                  const float* __restrict__ mask) {
    extern __shared__ char sm[];
    __half* sS   = (__half*)(sm + SM_S);
    __half* wB   = (__half*)(sm + SM_W);
    __half* xiS  = (__half*)(sm + SM_X);
    float*  part = (float*)(sm + SM_P);
    float*  mb2s = (float*)(sm + SM_B2);
    float*  mskJ = (float*)(sm + SM_MK);

    int tid = threadIdx.x;
    int b     = blockIdx.x >> 2;
    int ibase = (blockIdx.x & 3) << 5;

    for (int idx = tid; idx < 4096; idx += 256) {
        int r = idx >> 5, c = idx & 31;
        *(uint4*)&sS[r * ST_ + c * 8] = *(const uint4*)&g_S[((size_t)(b * N_ + r)) * H_ + c * 8];
        *(uint4*)&wB[r * ST_ + c * 8] = *(const uint4*)&g_WT[r * H_ + c * 8];
    }
    for (int idx = tid; idx < 1024; idx += 256) {
        int r = idx >> 5, c = idx & 31;
        *(uint4*)&xiS[r * 256 + c * 8] =
            *(const uint4*)&g_XI[((size_t)(b * N_ + ibase + r)) * H_ + c * 8];
    }
    if (tid < 128) { mb2s[tid] = mb2[tid]; mskJ[tid] = mask[b * N_ + tid]; }
    __syncthreads();

    int lane = tid & 31, w = tid >> 5;
    int mg = w >> 1, ng = w & 1;
    uint32_t aB = smem_u32(&sS[(mg * 32 + (lane & 15)) * ST_ + ((lane >> 4) & 1) * 8]);
    uint32_t bB = smem_u32(&wB[(ng * 64 + (lane & 15)) * ST_ + ((lane >> 4) & 1) * 8]);

    const __half2 z2 = __float2half2_rn(0.f);
    float mrow[2][2];
#pragma unroll
    for (int mt = 0; mt < 2; mt++) {
        mrow[mt][0] = mskJ[mg * 32 + mt * 16 + (lane >> 2)];
        mrow[mt][1] = mskJ[mg * 32 + mt * 16 + (lane >> 2) + 8];
    }

    for (int ip = 0; ip < 16; ip++) {
        float C[2][2][8][4] = {};            // [il][mt][nt][4]
        int i0 = ip * 2;

#pragma unroll 4
        for (int kt = 0; kt < 16; kt++) {
            uint32_t bf[4][4];
#pragma unroll
            for (int q = 0; q < 4; q++)
                ldsm_x4(bf[q], bB + q * (16 * ST_ * 2) + kt * 32);
            __half2 xA[2], xB[2];
#pragma unroll
            for (int il = 0; il < 2; il++) {
                const __half2* xp = (const __half2*)&xiS[(i0 + il) * 256 + kt * 16 + (lane & 3) * 2];
                xA[il] = xp[0];
                xB[il] = xp[4];
            }
#pragma unroll
            for (int mt = 0; mt < 2; mt++) {
                uint32_t sf[4];
                ldsm_x4(sf, aB + mt * (16 * ST_ * 2) + kt * 32);
#pragma unroll
                for (int il = 0; il < 2; il++) {
                    uint32_t a[4];
                    __half2 t;
                    t = __hmax2(__hadd2(*(__half2*)&sf[0], xA[il]), z2); a[0] = *(uint32_t*)&t;
                    t = __hmax2(__hadd2(*(__half2*)&sf[1], xA[il]), z2); a[1] = *(uint32_t*)&t;
                    t = __hmax2(__hadd2(*(__half2*)&sf[2], xB[il]), z2); a[2] = *(uint32_t*)&t;
                    t = __hmax2(__hadd2(*(__half2*)&sf[3], xB[il]), z2); a[3] = *(uint32_t*)&t;
#pragma unroll
                    for (int q = 0; q < 4; q++) {
                        mma16816(C[il][mt][q * 2],     a, bf[q][0], bf[q][2]);
                        mma16816(C[il][mt][q * 2 + 1], a, bf[q][1], bf[q][3]);
                    }
                }
            }
        }

        // epilogue: relu(+mb2)*mask_j, reduce rows (j) -> part, combine m-groups
#pragma unroll
        for (int il = 0; il < 2; il++) {
#pragma unroll
            for (int nt = 0; nt < 8; nt++) {
                int n = ng * 64 + (nt >> 1) * 16 + (nt & 1) * 8 + (lane & 3) * 2;
                float bn0 = mb2s[n], bn1 = mb2s[n + 1];
                float s0 = 0.f, s1 = 0.f;
#pragma unroll
                for (int mt = 0; mt < 2; mt++) {
                    s0 += fmaxf(C[il][mt][nt][0] + bn0, 0.f) * mrow[mt][0]
                        + fmaxf(C[il][mt][nt][2] + bn0, 0.f) * mrow[mt][1];
                    s1 += fmaxf(C[il][mt][nt][1] + bn1, 0.f) * mrow[mt][0]
                        + fmaxf(C[il][mt][nt][3] + bn1, 0.f) * mrow[mt][1];
                }
#pragma unroll
                for (int o = 4; o < 32; o <<= 1) {
                    s0 += __shfl_xor_sync(0xffffffffu, s0, o);
                    s1 += __shfl_xor_sync(0xffffffffu, s1, o);
                }
                if (lane < 4) {
                    part[(mg * 2 + il) * 128 + n]     = s0;
                    part[(mg * 2 + il) * 128 + n + 1] = s1;
                }
            }
        }
        __syncthreads();
        {
            int il = tid >> 7, c = tid & 127;
            float v = part[il * 128 + c] + part[(2 + il) * 128 + c]
                    + part[(4 + il) * 128 + c] + part[(6 + il) * 128 + c];
            g_AGGH[((size_t)(b * N_ + ibase + i0 + il)) * D_ + c] = __float2half(v);
        }
        __syncthreads();
    }
}

// ---------------- K3: update MLP + residual + mask (tensor cores) ----------------
// grid 128 x 32 rows, 8 warps = 2 mg x 4 nq
#define K3_A  0                          // 32 x 264 half (nodes_h | agg_h)
#define K3_U  16896                      // 32 x 264 half (u, fp16)
#define K3_B  33792                      // 256 x 264 half (U1T, then U2T)
#define K3_TOT 168960
__global__ __launch_bounds__(256) void k3_final(
    const float* __restrict__ nodes, const float* __restrict__ mask,
    const float* __restrict__ ub1, const float* __restrict__ ub2,
    float* __restrict__ out) {
    extern __shared__ char sm3[];
    __half* sA = (__half*)(sm3 + K3_A);
    __half* sU = (__half*)(sm3 + K3_U);
    __half* sB = (__half*)(sm3 + K3_B);
    int tid = threadIdx.x;
    int r0 = blockIdx.x * 32;

    for (int idx = tid; idx < 1024; idx += 256) {
        int r = idx >> 5, c = idx & 31;
        const __half* src = (c < 16) ? &g_NH[((size_t)(r0 + r)) * D_ + c * 8]
                                     : &g_AGGH[((size_t)(r0 + r)) * D_ + (c - 16) * 8];
        *(uint4*)&sA[r * ST_ + c * 8] = *(const uint4*)src;
    }
    for (int idx = tid; idx < 8192; idx += 256) {
        int r = idx >> 5, c = idx & 31;
        *(uint4*)&sB[r * ST_ + c * 8] = *(const uint4*)&g_U1T[r * 256 + c * 8];
    }
    __syncthreads();

    int lane = tid & 31, w = tid >> 5;
    int mg = w >> 2, nq = w & 3;

    // ---- stage 1: u = relu([nodes|agg] @ uw1 + ub1) ----
    {
        int n0 = nq * 64;
        uint32_t aB = smem_u32(&sA[(mg * 16 + (lane & 15)) * ST_ + ((lane >> 4) & 1) * 8]);
        uint32_t bB = smem_u32(&sB[(n0 + (lane & 15)) * ST_ + ((lane >> 4) & 1) * 8]);
        float C[8][4] = {};
#pragma unroll
        for (int kt = 0; kt < 16; kt++) {
            uint32_t am[4], bf[4][4];
            ldsm_x4(am, aB + kt * 32);
#pragma unroll
            for (int q = 0; q < 4; q++) ldsm_x4(bf[q], bB + q * (16 * ST_ * 2) + kt * 32);
#pragma unroll
            for (int q = 0; q < 4; q++) {
                mma16816(C[q * 2],     am, bf[q][0], bf[q][2]);
                mma16816(C[q * 2 + 1], am, bf[q][1], bf[q][3]);
            }
        }
#pragma unroll
        for (int q = 0; q < 4; q++) {
#pragma unroll
            for (int sub = 0; sub < 2; sub++) {
                int nt = q * 2 + sub;
                int col = n0 + q * 16 + sub * 8 + (lane & 3) * 2;
                float b0 = ub1[col], b1 = ub1[col + 1];
                int rowl = mg * 16 + (lane >> 2);
                *(__half2*)&sU[rowl * ST_ + col] =
                    __floats2half2_rn(fmaxf(C[nt][0] + b0, 0.f), fmaxf(C[nt][1] + b1, 0.f));
                *(__half2*)&sU[(rowl + 8) * ST_ + col] =
                    __floats2half2_rn(fmaxf(C[nt][2] + b0, 0.f), fmaxf(C[nt][3] + b1, 0.f));
            }
        }
    }
    __syncthreads();
    for (int idx = tid; idx < 4096; idx += 256) {
        int r = idx >> 5, c = idx & 31;
        *(uint4*)&sB[r * ST_ + c * 8] = *(const uint4*)&g_U2T[r * 256 + c * 8];
    }
    __syncthreads();

    // ---- stage 2: out = (nodes + u @ uw2 + ub2) * mask ----
    {
        int n0 = nq * 32;
        uint32_t aB = smem_u32(&sU[(mg * 16 + (lane & 15)) * ST_ + ((lane >> 4) & 1) * 8]);
        uint32_t bB = smem_u32(&sB[(n0 + (lane & 15)) * ST_ + ((lane >> 4) & 1) * 8]);
        float C[4][4] = {};
#pragma unroll
        for (int kt = 0; kt < 16; kt++) {
            uint32_t am[4], bf[2][4];
            ldsm_x4(am, aB + kt * 32);
#pragma unroll
            for (int q = 0; q < 2; q++) ldsm_x4(bf[q], bB + q * (16 * ST_ * 2) + kt * 32);
#pragma unroll
            for (int q = 0; q < 2; q++) {
                mma16816(C[q * 2],     am, bf[q][0], bf[q][2]);
                mma16816(C[q * 2 + 1], am, bf[q][1], bf[q][3]);
            }
        }
        int rowA = r0 + mg * 16 + (lane >> 2);
        float mk0 = mask[rowA], mk1 = mask[rowA + 8];
#pragma unroll
        for (int q = 0; q < 2; q++) {
#pragma unroll
            for (int sub = 0; sub < 2; sub++) {
                int nt = q * 2 + sub;
                int col = n0 + q * 16 + sub * 8 + (lane & 3) * 2;
                float b0 = ub2[col], b1 = ub2[col + 1];
                const float2 nv0 = *(const float2*)&nodes[(size_t)rowA * D_ + col];
                const float2 nv1 = *(const float2*)&nodes[(size_t)(rowA + 8) * D_ + col];
                float2 o0, o1;
                o0.x = (nv0.x + C[nt][0] + b0) * mk0;
                o0.y = (nv0.y + C[nt][1] + b1) * mk0;
                o1.x = (nv1.x + C[nt][2] + b0) * mk1;
                o1.y = (nv1.y + C[nt][3] + b1) * mk1;
                *(float2*)&out[(size_t)rowA * D_ + col]       = o0;
                *(float2*)&out[(size_t)(rowA + 8) * D_ + col] = o1;
            }
        }
    }
}

// ---------------- launch ----------------
extern "C" void kernel_launch(void* const* d_in, const int* in_sizes, int n_in,
                              void* d_out, int out_size) {
    const float* nodes = (const float*)d_in[0];
    const float* mask  = (const float*)d_in[1];
    const float* ln_g  = (const float*)d_in[2];
    const float* ln_b  = (const float*)d_in[3];
    const float* mw1   = (const float*)d_in[4];
    const float* mb1   = (const float*)d_in[5];
    const float* mw2   = (const float*)d_in[6];
    const float* mb2   = (const float*)d_in[7];
    const float* uw1   = (const float*)d_in[8];
    const float* ub1   = (const float*)d_in[9];
    const float* uw2   = (const float*)d_in[10];
    const float* ub2   = (const float*)d_in[11];
    float* out = (float*)d_out;

    cudaFuncSetAttribute(k1_proj,  cudaFuncAttributeMaxDynamicSharedMemorySize, K1_TOT);
    cudaFuncSetAttribute(k2_main,  cudaFuncAttributeMaxDynamicSharedMemorySize, SM_TOT);
    cudaFuncSetAttribute(k3_final, cudaFuncAttributeMaxDynamicSharedMemorySize, K3_TOT);

    kw<<<2816, 256>>>(nodes, mw1, mw2, uw1, uw2);
    k1_proj<<<128, 256, K1_TOT>>>(nodes, mask, ln_g, ln_b, mb1);
    k2_main<<<128, 256, SM_TOT>>>(mb2, mask);
    k3_final<<<128, 256, K3_TOT>>>(nodes, mask, ub1, ub2, out);
}

// round 5
// speedup vs baseline: 2.1446x; 1.2691x over previous
#include <cuda_runtime.h>
#include <cuda_fp16.h>
#include <cstdint>

#define B_ 32
#define N_ 128
#define D_ 128
#define H_ 256
#define ROWS_ (B_ * N_)       // 4096
#define ST_ 264               // stride (halves) for K=256 tiles: 528B, mod128=16 -> conflict-free ldsm
#define ST1 136               // stride (halves) for K=128 tiles

// ---------------- scratch (device globals; no allocation allowed) ----------------
__device__ __half g_XI[ROWS_ * H_];      // receiver projection x@mw1[:D]
__device__ __half g_S [ROWS_ * H_];      // sender projection x@mw1[D:] + mb1
__device__ __half g_WT [D_ * H_];        // mw2^T: [d][h]
__device__ __half g_W1Ta[H_ * D_];       // mw1[:D]^T:  [h][k]
__device__ __half g_W1Tb[H_ * D_];       // mw1[D:]^T:  [h][k]
__device__ __half g_U1T[H_ * 2 * D_];    // uw1^T: [h][k] k=256
__device__ __half g_U2T[D_ * H_];        // uw2^T: [d][k] k=256
__device__ __half g_NH [ROWS_ * D_];     // nodes fp16
__device__ __half g_AGGH[ROWS_ * D_];    // aggregated messages fp16

// ---------------- helpers ----------------
__device__ __forceinline__ uint32_t smem_u32(const void* p) {
    return (uint32_t)__cvta_generic_to_shared(p);
}
__device__ __forceinline__ void cp16(void* s, const void* g) {
    asm volatile("cp.async.cg.shared.global [%0], [%1], 16;" :: "r"(smem_u32(s)), "l"(g));
}
__device__ __forceinline__ void cp_commit_wait() {
    asm volatile("cp.async.commit_group;\n\tcp.async.wait_group 0;" ::: "memory");
}
__device__ __forceinline__ void ldsm_x4(uint32_t r[4], uint32_t addr) {
    asm volatile("ldmatrix.sync.aligned.m8n8.x4.shared.b16 {%0,%1,%2,%3}, [%4];"
                 : "=r"(r[0]), "=r"(r[1]), "=r"(r[2]), "=r"(r[3]) : "r"(addr));
}
__device__ __forceinline__ void mma16816(float c[4], const uint32_t a[4], uint32_t b0, uint32_t b1) {
    asm volatile("mma.sync.aligned.m16n8k16.row.col.f32.f16.f16.f32 "
                 "{%0,%1,%2,%3}, {%4,%5,%6,%7}, {%8,%9}, {%0,%1,%2,%3};"
                 : "+f"(c[0]), "+f"(c[1]), "+f"(c[2]), "+f"(c[3])
                 : "r"(a[0]), "r"(a[1]), "r"(a[2]), "r"(a[3]), "r"(b0), "r"(b1));
}

// ---------------- KW: coalesced tiled transposes + nodes->fp16 ----------------
__global__ void kw(const float* __restrict__ nodes, const float* __restrict__ mw1,
                   const float* __restrict__ mw2, const float* __restrict__ uw1,
                   const float* __restrict__ uw2) {
    __shared__ float tile[32][33];
    int bid = blockIdx.x, tid = threadIdx.x;
    if (bid < 512) {           // nodes -> fp16, coalesced
        int idx = bid * 1024 + tid * 4;
        float4 v = *(const float4*)&nodes[idx];
        __half2* o = (__half2*)&g_NH[idx];
        o[0] = __floats2half2_rn(v.x, v.y);
        o[1] = __floats2half2_rn(v.z, v.w);
        return;
    }
    int t = bid - 512;
    const float* src; __half* dst; int srcLd, dstLd, tr, tc;
    if (t < 32)       { src = mw1;            dst = g_W1Ta; srcLd = 256; dstLd = 128; tr = t >> 3;  tc = t & 7; }
    else if (t < 64)  { t -= 32; src = mw1 + 128 * 256; dst = g_W1Tb; srcLd = 256; dstLd = 128; tr = t >> 3; tc = t & 7; }
    else if (t < 96)  { t -= 64; src = mw2;   dst = g_WT;   srcLd = 128; dstLd = 256; tr = t >> 2;  tc = t & 3; }
    else if (t < 160) { t -= 96; src = uw1;   dst = g_U1T;  srcLd = 256; dstLd = 256; tr = t >> 3;  tc = t & 7; }
    else              { t -= 160; src = uw2;  dst = g_U2T;  srcLd = 128; dstLd = 256; tr = t >> 2;  tc = t & 3; }
    int r0 = tr * 32, c0 = tc * 32;
    int lr = tid >> 3, lc = (tid & 7) * 4;
    float4 v = *(const float4*)&src[(size_t)(r0 + lr) * srcLd + c0 + lc];
    tile[lr][lc] = v.x; tile[lr][lc + 1] = v.y; tile[lr][lc + 2] = v.z; tile[lr][lc + 3] = v.w;
    __syncthreads();
    __half2 p0 = __floats2half2_rn(tile[lc][lr],     tile[lc + 1][lr]);
    __half2 p1 = __floats2half2_rn(tile[lc + 2][lr], tile[lc + 3][lr]);
    __half2* o = (__half2*)&dst[(size_t)(c0 + lr) * dstLd + r0 + lc];
    o[0] = p0; o[1] = p1;
}

// ---------------- K1: fused LayerNorm + mma projections ----------------
#define K1_XH 0
#define K1_BA 8704
#define K1_BB 78336
#define K1_TOT 147968
__global__ __launch_bounds__(256) void k1_proj(const float* __restrict__ nodes,
                                               const float* __restrict__ mask,
                                               const float* __restrict__ gam,
                                               const float* __restrict__ bet,
                                               const float* __restrict__ mb1) {
    extern __shared__ char sm1[];
    __half* xh = (__half*)(sm1 + K1_XH);
    __half* Ba = (__half*)(sm1 + K1_BA);
    __half* Bb = (__half*)(sm1 + K1_BB);
    int tid = threadIdx.x;
    int r0 = blockIdx.x * 32;

    for (int idx = tid; idx < 4096; idx += 256) {
        int r = idx >> 4, c = idx & 15;
        cp16(&Ba[r * ST1 + c * 8], &g_W1Ta[r * 128 + c * 8]);
        cp16(&Bb[r * ST1 + c * 8], &g_W1Tb[r * 128 + c * 8]);
    }

    {   // fused LayerNorm * mask -> xh (fp16)
        int row = tid >> 3, p = tid & 7;
        const float* np = &nodes[(size_t)(r0 + row) * D_ + p * 16];
        float4 v[4];
#pragma unroll
        for (int q = 0; q < 4; q++) v[q] = *(const float4*)&np[q * 4];
        float s = 0.f, s2 = 0.f;
#pragma unroll
        for (int q = 0; q < 4; q++) {
            s  += v[q].x + v[q].y + v[q].z + v[q].w;
            s2 += v[q].x*v[q].x + v[q].y*v[q].y + v[q].z*v[q].z + v[q].w*v[q].w;
        }
#pragma unroll
        for (int o = 1; o < 8; o <<= 1) {
            s  += __shfl_xor_sync(0xffffffffu, s,  o);
            s2 += __shfl_xor_sync(0xffffffffu, s2, o);
        }
        float mu  = s * (1.0f / 128.0f);
        float var = s2 * (1.0f / 128.0f) - mu * mu;
        float rs  = rsqrtf(var + 1e-5f);
        float m   = mask[r0 + row];
        __half* xo = &xh[row * ST1 + p * 16];
        const float* gp = &gam[p * 16];
        const float* bp = &bet[p * 16];
        const float* vv = (const float*)v;
#pragma unroll
        for (int q = 0; q < 16; q++)
            xo[q] = __float2half(((vv[q] - mu) * rs * gp[q] + bp[q]) * m);
    }
    cp_commit_wait();
    __syncthreads();

    int lane = tid & 31, w = tid >> 5;
    int isS = w >> 2, nq = w & 3, n0 = nq * 64;
    const __half* Bsel = isS ? Bb : Ba;
    uint32_t aB = smem_u32(&xh[(lane & 15) * ST1 + ((lane >> 4) & 1) * 8]);
    uint32_t bB = smem_u32(&Bsel[(n0 + (lane & 15)) * ST1 + ((lane >> 4) & 1) * 8]);

    float C[2][8][4] = {};
#pragma unroll
    for (int kt = 0; kt < 8; kt++) {
        uint32_t am[2][4], bf[4][4];
#pragma unroll
        for (int mt = 0; mt < 2; mt++) ldsm_x4(am[mt], aB + mt * (16 * ST1 * 2) + kt * 32);
#pragma unroll
        for (int q = 0; q < 4; q++) ldsm_x4(bf[q], bB + q * (16 * ST1 * 2) + kt * 32);
#pragma unroll
        for (int mt = 0; mt < 2; mt++)
#pragma unroll
            for (int q = 0; q < 4; q++) {
                mma16816(C[mt][q * 2],     am[mt], bf[q][0], bf[q][2]);
                mma16816(C[mt][q * 2 + 1], am[mt], bf[q][1], bf[q][3]);
            }
    }

    __half* dst = isS ? g_S : g_XI;
#pragma unroll
    for (int mt = 0; mt < 2; mt++) {
#pragma unroll
        for (int q = 0; q < 4; q++) {
#pragma unroll
            for (int sub = 0; sub < 2; sub++) {
                int nt = q * 2 + sub;
                int col = n0 + q * 16 + sub * 8 + (lane & 3) * 2;
                float b0 = 0.f, b1 = 0.f;
                if (isS) { b0 = mb1[col]; b1 = mb1[col + 1]; }
                int rowA = r0 + mt * 16 + (lane >> 2);
                *(__half2*)&dst[(size_t)rowA * H_ + col] =
                    __floats2half2_rn(C[mt][nt][0] + b0, C[mt][nt][1] + b1);
                *(__half2*)&dst[(size_t)(rowA + 8) * H_ + col] =
                    __floats2half2_rn(C[mt][nt][2] + b0, C[mt][nt][3] + b1);
            }
        }
    }
}

// ---------------- K2: A-stationary edge-MLP GEMM (mma.sync, no in-loop barriers) ----------------
// grid = 128 (b = bx>>2, ibase = (bx&3)*32), 256 threads = 8 warps:
// mw = wid&3 -> d rows [mw*32, mw*32+32);  jg = wid>>2 -> j in [jg*64, jg*64+64).
// Per i: C[d][j] = sum_k WT[d][k] * relu(s[j][k] + xi[i][k]); epilogue reduces j thread-locally.
#define K2_S   0                         // 128 x 264 half  (s rows)
#define K2_W   67584                     // 128 x 264 half  (WT rows)
#define K2_X   135168                    // 32 x 256 half   (xi rows)
#define K2_P   151552                    // part[2][32][128] float
#define K2_MSK 184320                    // 128 float
#define K2_TOT 184832

__global__ __launch_bounds__(256, 1) void k2_main(const float* __restrict__ mb2,
                                                  const float* __restrict__ mask) {
    extern __shared__ char sm[];
    __half* sS  = (__half*)(sm + K2_S);
    __half* wT  = (__half*)(sm + K2_W);
    __half* xiS = (__half*)(sm + K2_X);
    float*  part = (float*)(sm + K2_P);
    float*  mskJ = (float*)(sm + K2_MSK);

    int tid = threadIdx.x;
    int b     = blockIdx.x >> 2;
    int ibase = (blockIdx.x & 3) << 5;

    for (int idx = tid; idx < 4096; idx += 256) {
        int r = idx >> 5, c = idx & 31;
        cp16(&sS[r * ST_ + c * 8], &g_S[((size_t)(b * N_ + r)) * H_ + c * 8]);
        cp16(&wT[r * ST_ + c * 8], &g_WT[(size_t)r * H_ + c * 8]);
    }
    for (int idx = tid; idx < 1024; idx += 256)
        cp16(&xiS[idx * 8], &g_XI[((size_t)(b * N_ + ibase)) * H_ + idx * 8]);
    if (tid < 32) cp16(&mskJ[tid * 4], &mask[b * N_ + tid * 4]);
    cp_commit_wait();
    __syncthreads();

    int lane = tid & 31, w = tid >> 5;
    int mw = w & 3, jg = w >> 2;

    uint32_t aB  = smem_u32(&wT[(mw * 32 + (lane & 15)) * ST_ + ((lane >> 4) & 1) * 8]);
    uint32_t aB1 = aB + 16 * ST_ * 2;
    uint32_t bB  = smem_u32(&sS[(jg * 64 + (lane & 15)) * ST_ + ((lane >> 4) & 1) * 8]);

    float bias[2][2];
    bias[0][0] = mb2[mw * 32 + (lane >> 2)];
    bias[0][1] = mb2[mw * 32 + (lane >> 2) + 8];
    bias[1][0] = mb2[mw * 32 + 16 + (lane >> 2)];
    bias[1][1] = mb2[mw * 32 + 16 + (lane >> 2) + 8];
    float2 mj[8];
#pragma unroll
    for (int nt = 0; nt < 8; nt++) {
        int j = jg * 64 + nt * 8 + (lane & 3) * 2;
        mj[nt].x = mskJ[j]; mj[nt].y = mskJ[j + 1];
    }

    const __half2 z2 = __float2half2_rn(0.f);
    float* pbase = part + jg * 4096 + mw * 32;

    for (int i = 0; i < 32; i++) {
        float C[2][8][4] = {};            // [mt][nt][4]
#pragma unroll
        for (int kt = 0; kt < 16; kt++) {
            uint32_t a0[4], a1[4];
            ldsm_x4(a0, aB  + kt * 32);
            ldsm_x4(a1, aB1 + kt * 32);
            __half2 xA = *(const __half2*)&xiS[i * 256 + kt * 16 + (lane & 3) * 2];
            __half2 xB = *(const __half2*)&xiS[i * 256 + kt * 16 + (lane & 3) * 2 + 8];
#pragma unroll
            for (int q = 0; q < 4; q++) {
                uint32_t bf[4];
                ldsm_x4(bf, bB + q * (16 * ST_ * 2) + kt * 32);
                __half2 t;
                t = __hmax2(__hadd2(*(__half2*)&bf[0], xA), z2); bf[0] = *(uint32_t*)&t;
                t = __hmax2(__hadd2(*(__half2*)&bf[1], xA), z2); bf[1] = *(uint32_t*)&t;
                t = __hmax2(__hadd2(*(__half2*)&bf[2], xB), z2); bf[2] = *(uint32_t*)&t;
                t = __hmax2(__hadd2(*(__half2*)&bf[3], xB), z2); bf[3] = *(uint32_t*)&t;
                mma16816(C[0][q * 2],     a0, bf[0], bf[2]);
                mma16816(C[0][q * 2 + 1], a0, bf[1], bf[3]);
                mma16816(C[1][q * 2],     a1, bf[0], bf[2]);
                mma16816(C[1][q * 2 + 1], a1, bf[1], bf[3]);
            }
        }
        // epilogue: thread-local j reduction
        float s00 = 0.f, s01 = 0.f, s10 = 0.f, s11 = 0.f;
#pragma unroll
        for (int nt = 0; nt < 8; nt++) {
            s00 += fmaxf(C[0][nt][0] + bias[0][0], 0.f) * mj[nt].x
                 + fmaxf(C[0][nt][1] + bias[0][0], 0.f) * mj[nt].y;
            s01 += fmaxf(C[0][nt][2] + bias[0][1], 0.f) * mj[nt].x
                 + fmaxf(C[0][nt][3] + bias[0][1], 0.f) * mj[nt].y;
            s10 += fmaxf(C[1][nt][0] + bias[1][0], 0.f) * mj[nt].x
                 + fmaxf(C[1][nt][1] + bias[1][0], 0.f) * mj[nt].y;
            s11 += fmaxf(C[1][nt][2] + bias[1][1], 0.f) * mj[nt].x
                 + fmaxf(C[1][nt][3] + bias[1][1], 0.f) * mj[nt].y;
        }
#pragma unroll
        for (int o = 1; o < 4; o <<= 1) {
            s00 += __shfl_xor_sync(0xffffffffu, s00, o);
            s01 += __shfl_xor_sync(0xffffffffu, s01, o);
            s10 += __shfl_xor_sync(0xffffffffu, s10, o);
            s11 += __shfl_xor_sync(0xffffffffu, s11, o);
        }
        if ((lane & 3) == 0) {
            float* pp = pbase + i * 128;
            int r = lane >> 2;
            pp[r] = s00; pp[r + 8] = s01; pp[r + 16] = s10; pp[r + 24] = s11;
        }
    }
    __syncthreads();
    for (int idx = tid; idx < 2048; idx += 256) {
        int i = idx >> 6, dp = (idx & 63) * 2;
        float v0 = part[i * 128 + dp]     + part[4096 + i * 128 + dp];
        float v1 = part[i * 128 + dp + 1] + part[4096 + i * 128 + dp + 1];
        *(__half2*)&g_AGGH[((size_t)(b * N_ + ibase + i)) * D_ + dp] = __floats2half2_rn(v0, v1);
    }
}

// ---------------- K3: update MLP + residual + mask (tensor cores) ----------------
#define K3_A  0
#define K3_U  16896
#define K3_B  33792
#define K3_TOT 168960
__global__ __launch_bounds__(256) void k3_final(
    const float* __restrict__ nodes, const float* __restrict__ mask,
    const float* __restrict__ ub1, const float* __restrict__ ub2,
    float* __restrict__ out) {
    extern __shared__ char sm3[];
    __half* sA = (__half*)(sm3 + K3_A);
    __half* sU = (__half*)(sm3 + K3_U);
    __half* sB = (__half*)(sm3 + K3_B);
    int tid = threadIdx.x;
    int r0 = blockIdx.x * 32;

    for (int idx = tid; idx < 1024; idx += 256) {
        int r = idx >> 5, c = idx & 31;
        const __half* src = (c < 16) ? &g_NH[((size_t)(r0 + r)) * D_ + c * 8]
                                     : &g_AGGH[((size_t)(r0 + r)) * D_ + (c - 16) * 8];
        cp16(&sA[r * ST_ + c * 8], src);
    }
    for (int idx = tid; idx < 8192; idx += 256) {
        int r = idx >> 5, c = idx & 31;
        cp16(&sB[r * ST_ + c * 8], &g_U1T[r * 256 + c * 8]);
    }
    cp_commit_wait();
    __syncthreads();

    int lane = tid & 31, w = tid >> 5;
    int mg = w >> 2, nq = w & 3;

    // ---- stage 1: u = relu([nodes|agg] @ uw1 + ub1) ----
    {
        int n0 = nq * 64;
        uint32_t aB = smem_u32(&sA[(mg * 16 + (lane & 15)) * ST_ + ((lane >> 4) & 1) * 8]);
        uint32_t bB = smem_u32(&sB[(n0 + (lane & 15)) * ST_ + ((lane >> 4) & 1) * 8]);
        float C[8][4] = {};
#pragma unroll
        for (int kt = 0; kt < 16; kt++) {
            uint32_t am[4], bf[4][4];
            ldsm_x4(am, aB + kt * 32);
#pragma unroll
            for (int q = 0; q < 4; q++) ldsm_x4(bf[q], bB + q * (16 * ST_ * 2) + kt * 32);
#pragma unroll
            for (int q = 0; q < 4; q++) {
                mma16816(C[q * 2],     am, bf[q][0], bf[q][2]);
                mma16816(C[q * 2 + 1], am, bf[q][1], bf[q][3]);
            }
        }
#pragma unroll
        for (int q = 0; q < 4; q++) {
#pragma unroll
            for (int sub = 0; sub < 2; sub++) {
                int nt = q * 2 + sub;
                int col = n0 + q * 16 + sub * 8 + (lane & 3) * 2;
                float b0 = ub1[col], b1 = ub1[col + 1];
                int rowl = mg * 16 + (lane >> 2);
                *(__half2*)&sU[rowl * ST_ + col] =
                    __floats2half2_rn(fmaxf(C[nt][0] + b0, 0.f), fmaxf(C[nt][1] + b1, 0.f));
                *(__half2*)&sU[(rowl + 8) * ST_ + col] =
                    __floats2half2_rn(fmaxf(C[nt][2] + b0, 0.f), fmaxf(C[nt][3] + b1, 0.f));
            }
        }
    }
    __syncthreads();
    for (int idx = tid; idx < 4096; idx += 256) {
        int r = idx >> 5, c = idx & 31;
        cp16(&sB[r * ST_ + c * 8], &g_U2T[r * 256 + c * 8]);
    }
    cp_commit_wait();
    __syncthreads();

    // ---- stage 2: out = (nodes + u @ uw2 + ub2) * mask ----
    {
        int n0 = nq * 32;
        uint32_t aB = smem_u32(&sU[(mg * 16 + (lane & 15)) * ST_ + ((lane >> 4) & 1) * 8]);
        uint32_t bB = smem_u32(&sB[(n0 + (lane & 15)) * ST_ + ((lane >> 4) & 1) * 8]);
        float C[4][4] = {};
#pragma unroll
        for (int kt = 0; kt < 16; kt++) {
            uint32_t am[4], bf[2][4];
            ldsm_x4(am, aB + kt * 32);
#pragma unroll
            for (int q = 0; q < 2; q++) ldsm_x4(bf[q], bB + q * (16 * ST_ * 2) + kt * 32);
#pragma unroll
            for (int q = 0; q < 2; q++) {
                mma16816(C[q * 2],     am, bf[q][0], bf[q][2]);
                mma16816(C[q * 2 + 1], am, bf[q][1], bf[q][3]);
            }
        }
        int rowA = r0 + mg * 16 + (lane >> 2);
        float mk0 = mask[rowA], mk1 = mask[rowA + 8];
#pragma unroll
        for (int q = 0; q < 2; q++) {
#pragma unroll
            for (int sub = 0; sub < 2; sub++) {
                int nt = q * 2 + sub;
                int col = n0 + q * 16 + sub * 8 + (lane & 3) * 2;
                float b0 = ub2[col], b1 = ub2[col + 1];
                const float2 nv0 = *(const float2*)&nodes[(size_t)rowA * D_ + col];
                const float2 nv1 = *(const float2*)&nodes[(size_t)(rowA + 8) * D_ + col];
                float2 o0, o1;
                o0.x = (nv0.x + C[nt][0] + b0) * mk0;
                o0.y = (nv0.y + C[nt][1] + b1) * mk0;
                o1.x = (nv1.x + C[nt][2] + b0) * mk1;
                o1.y = (nv1.y + C[nt][3] + b1) * mk1;
                *(float2*)&out[(size_t)rowA * D_ + col]       = o0;
                *(float2*)&out[(size_t)(rowA + 8) * D_ + col] = o1;
            }
        }
    }
}

// ---------------- launch ----------------
extern "C" void kernel_launch(void* const* d_in, const int* in_sizes, int n_in,
                              void* d_out, int out_size) {
    const float* nodes = (const float*)d_in[0];
    const float* mask  = (const float*)d_in[1];
    const float* ln_g  = (const float*)d_in[2];
    const float* ln_b  = (const float*)d_in[3];
    const float* mw1   = (const float*)d_in[4];
    const float* mb1   = (const float*)d_in[5];
    const float* mw2   = (const float*)d_in[6];
    const float* mb2   = (const float*)d_in[7];
    const float* uw1   = (const float*)d_in[8];
    const float* ub1   = (const float*)d_in[9];
    const float* uw2   = (const float*)d_in[10];
    const float* ub2   = (const float*)d_in[11];
    float* out = (float*)d_out;

    cudaFuncSetAttribute(k1_proj,  cudaFuncAttributeMaxDynamicSharedMemorySize, K1_TOT);
    cudaFuncSetAttribute(k2_main,  cudaFuncAttributeMaxDynamicSharedMemorySize, K2_TOT);
    cudaFuncSetAttribute(k3_final, cudaFuncAttributeMaxDynamicSharedMemorySize, K3_TOT);

    kw<<<704, 256>>>(nodes, mw1, mw2, uw1, uw2);
    k1_proj<<<128, 256, K1_TOT>>>(nodes, mask, ln_g, ln_b, mb1);
    k2_main<<<128, 256, K2_TOT>>>(mb2, mask);
    k3_final<<<128, 256, K3_TOT>>>(nodes, mask, ub1, ub2, out);
}

// round 6
// speedup vs baseline: 2.2533x; 1.0507x over previous
#include <cuda_runtime.h>
#include <cuda_fp16.h>
#include <cstdint>

#define B_ 32
#define N_ 128
#define D_ 128
#define H_ 256
#define ROWS_ (B_ * N_)       // 4096
#define ST_ 264               // stride (halves) for K=256 tiles: 528B, mod128=16 -> conflict-free ldsm
#define ST1 136               // stride (halves) for K=128 tiles

// ---------------- scratch (device globals; no allocation allowed) ----------------
__device__ __half g_XI[ROWS_ * H_];      // receiver projection x@mw1[:D]
__device__ __half g_S [ROWS_ * H_];      // sender projection x@mw1[D:] + mb1
__device__ __half g_WT [D_ * H_];        // mw2^T: [d][h]
__device__ __half g_W1Ta[H_ * D_];       // mw1[:D]^T:  [h][k]
__device__ __half g_W1Tb[H_ * D_];       // mw1[D:]^T:  [h][k]
__device__ __half g_U1T[H_ * 2 * D_];    // uw1^T: [h][k] k=256
__device__ __half g_U2T[D_ * H_];        // uw2^T: [d][k] k=256
__device__ __half g_NH [ROWS_ * D_];     // nodes fp16
__device__ __half g_AGGH[ROWS_ * D_];    // aggregated messages fp16

// ---------------- helpers ----------------
__device__ __forceinline__ uint32_t smem_u32(const void* p) {
    return (uint32_t)__cvta_generic_to_shared(p);
}
__device__ __forceinline__ void cp16(void* s, const void* g) {
    asm volatile("cp.async.cg.shared.global [%0], [%1], 16;" :: "r"(smem_u32(s)), "l"(g));
}
__device__ __forceinline__ void cp_commit() {
    asm volatile("cp.async.commit_group;" ::: "memory");
}
template <int N>
__device__ __forceinline__ void cp_wait() {
    asm volatile("cp.async.wait_group %0;" :: "n"(N) : "memory");
}
__device__ __forceinline__ void ldsm_x4(uint32_t r[4], uint32_t addr) {
    asm volatile("ldmatrix.sync.aligned.m8n8.x4.shared.b16 {%0,%1,%2,%3}, [%4];"
                 : "=r"(r[0]), "=r"(r[1]), "=r"(r[2]), "=r"(r[3]) : "r"(addr));
}
__device__ __forceinline__ void mma16816(float c[4], const uint32_t a[4], uint32_t b0, uint32_t b1) {
    asm volatile("mma.sync.aligned.m16n8k16.row.col.f32.f16.f16.f32 "
                 "{%0,%1,%2,%3}, {%4,%5,%6,%7}, {%8,%9}, {%0,%1,%2,%3};"
                 : "+f"(c[0]), "+f"(c[1]), "+f"(c[2]), "+f"(c[3])
                 : "r"(a[0]), "r"(a[1]), "r"(a[2]), "r"(a[3]), "r"(b0), "r"(b1));
}

// ---------------- KW: coalesced tiled transposes + nodes->fp16 ----------------
__global__ void kw(const float* __restrict__ nodes, const float* __restrict__ mw1,
                   const float* __restrict__ mw2, const float* __restrict__ uw1,
                   const float* __restrict__ uw2) {
    __shared__ float tile[32][33];
    int bid = blockIdx.x, tid = threadIdx.x;
    if (bid < 512) {           // nodes -> fp16, coalesced
        int idx = bid * 1024 + tid * 4;
        float4 v = *(const float4*)&nodes[idx];
        __half2* o = (__half2*)&g_NH[idx];
        o[0] = __floats2half2_rn(v.x, v.y);
        o[1] = __floats2half2_rn(v.z, v.w);
        return;
    }
    int t = bid - 512;
    const float* src; __half* dst; int srcLd, dstLd, tr, tc;
    if (t < 32)       { src = mw1;            dst = g_W1Ta; srcLd = 256; dstLd = 128; tr = t >> 3;  tc = t & 7; }
    else if (t < 64)  { t -= 32; src = mw1 + 128 * 256; dst = g_W1Tb; srcLd = 256; dstLd = 128; tr = t >> 3; tc = t & 7; }
    else if (t < 96)  { t -= 64; src = mw2;   dst = g_WT;   srcLd = 128; dstLd = 256; tr = t >> 2;  tc = t & 3; }
    else if (t < 160) { t -= 96; src = uw1;   dst = g_U1T;  srcLd = 256; dstLd = 256; tr = t >> 3;  tc = t & 7; }
    else              { t -= 160; src = uw2;  dst = g_U2T;  srcLd = 128; dstLd = 256; tr = t >> 2;  tc = t & 3; }
    int r0 = tr * 32, c0 = tc * 32;
    int lr = tid >> 3, lc = (tid & 7) * 4;
    float4 v = *(const float4*)&src[(size_t)(r0 + lr) * srcLd + c0 + lc];
    tile[lr][lc] = v.x; tile[lr][lc + 1] = v.y; tile[lr][lc + 2] = v.z; tile[lr][lc + 3] = v.w;
    __syncthreads();
    __half2 p0 = __floats2half2_rn(tile[lc][lr],     tile[lc + 1][lr]);
    __half2 p1 = __floats2half2_rn(tile[lc + 2][lr], tile[lc + 3][lr]);
    __half2* o = (__half2*)&dst[(size_t)(c0 + lr) * dstLd + r0 + lc];
    o[0] = p0; o[1] = p1;
}

// ---------------- K1: fused LayerNorm + mma projections ----------------
#define K1_XH 0
#define K1_BA 8704
#define K1_BB 78336
#define K1_TOT 147968
__global__ __launch_bounds__(256) void k1_proj(const float* __restrict__ nodes,
                                               const float* __restrict__ mask,
                                               const float* __restrict__ gam,
                                               const float* __restrict__ bet,
                                               const float* __restrict__ mb1) {
    extern __shared__ char sm1[];
    __half* xh = (__half*)(sm1 + K1_XH);
    __half* Ba = (__half*)(sm1 + K1_BA);
    __half* Bb = (__half*)(sm1 + K1_BB);
    int tid = threadIdx.x;
    int r0 = blockIdx.x * 32;

    for (int idx = tid; idx < 4096; idx += 256) {
        int r = idx >> 4, c = idx & 15;
        cp16(&Ba[r * ST1 + c * 8], &g_W1Ta[r * 128 + c * 8]);
        cp16(&Bb[r * ST1 + c * 8], &g_W1Tb[r * 128 + c * 8]);
    }
    cp_commit();

    {   // fused LayerNorm * mask -> xh (fp16)
        int row = tid >> 3, p = tid & 7;
        const float* np = &nodes[(size_t)(r0 + row) * D_ + p * 16];
        float4 v[4];
#pragma unroll
        for (int q = 0; q < 4; q++) v[q] = *(const float4*)&np[q * 4];
        float s = 0.f, s2 = 0.f;
#pragma unroll
        for (int q = 0; q < 4; q++) {
            s  += v[q].x + v[q].y + v[q].z + v[q].w;
            s2 += v[q].x*v[q].x + v[q].y*v[q].y + v[q].z*v[q].z + v[q].w*v[q].w;
        }
#pragma unroll
        for (int o = 1; o < 8; o <<= 1) {
            s  += __shfl_xor_sync(0xffffffffu, s,  o);
            s2 += __shfl_xor_sync(0xffffffffu, s2, o);
        }
        float mu  = s * (1.0f / 128.0f);
        float var = s2 * (1.0f / 128.0f) - mu * mu;
        float rs  = rsqrtf(var + 1e-5f);
        float m   = mask[r0 + row];
        __half* xo = &xh[row * ST1 + p * 16];
        const float* gp = &gam[p * 16];
        const float* bp = &bet[p * 16];
        const float* vv = (const float*)v;
#pragma unroll
        for (int q = 0; q < 16; q++)
            xo[q] = __float2half(((vv[q] - mu) * rs * gp[q] + bp[q]) * m);
    }
    cp_wait<0>();
    __syncthreads();

    int lane = tid & 31, w = tid >> 5;
    int isS = w >> 2, nq = w & 3, n0 = nq * 64;
    const __half* Bsel = isS ? Bb : Ba;
    uint32_t aB = smem_u32(&xh[(lane & 15) * ST1 + ((lane >> 4) & 1) * 8]);
    uint32_t bB = smem_u32(&Bsel[(n0 + (lane & 15)) * ST1 + ((lane >> 4) & 1) * 8]);

    float C[2][8][4] = {};
#pragma unroll
    for (int kt = 0; kt < 8; kt++) {
        uint32_t am[2][4], bf[4][4];
#pragma unroll
        for (int mt = 0; mt < 2; mt++) ldsm_x4(am[mt], aB + mt * (16 * ST1 * 2) + kt * 32);
#pragma unroll
        for (int q = 0; q < 4; q++) ldsm_x4(bf[q], bB + q * (16 * ST1 * 2) + kt * 32);
#pragma unroll
        for (int mt = 0; mt < 2; mt++)
#pragma unroll
            for (int q = 0; q < 4; q++) {
                mma16816(C[mt][q * 2],     am[mt], bf[q][0], bf[q][2]);
                mma16816(C[mt][q * 2 + 1], am[mt], bf[q][1], bf[q][3]);
            }
    }

    __half* dst = isS ? g_S : g_XI;
#pragma unroll
    for (int mt = 0; mt < 2; mt++) {
#pragma unroll
        for (int q = 0; q < 4; q++) {
#pragma unroll
            for (int sub = 0; sub < 2; sub++) {
                int nt = q * 2 + sub;
                int col = n0 + q * 16 + sub * 8 + (lane & 3) * 2;
                float b0 = 0.f, b1 = 0.f;
                if (isS) { b0 = mb1[col]; b1 = mb1[col + 1]; }
                int rowA = r0 + mt * 16 + (lane >> 2);
                *(__half2*)&dst[(size_t)rowA * H_ + col] =
                    __floats2half2_rn(C[mt][nt][0] + b0, C[mt][nt][1] + b1);
                *(__half2*)&dst[(size_t)(rowA + 8) * H_ + col] =
                    __floats2half2_rn(C[mt][nt][2] + b0, C[mt][nt][3] + b1);
            }
        }
    }
}

// ---------------- K2: A-stationary edge-MLP GEMM, (2m x 4j) warp tiling, i-pairs ----------------
// grid = 128 (b = bx>>2, ibase = (bx&3)*32), 256 threads = 8 warps:
// mw = wid&1 -> d rows [mw*64, mw*64+64);  jg = wid>>1 -> j in [jg*32, jg*32+32).
// Per i: C[d][j] = sum_k WT[d][k] * relu(s[j][k] + xi[i][k]); thread-local j reduction.
#define K2_S   0                         // 128 x 264 half (s rows)       67584 B
#define K2_W   67584                     // 128 x 264 half (WT rows)      67584 B
#define K2_X   135168                    // 32 x 256 half  (xi rows)      16384 B
#define K2_P   151552                    // part[4][32][128] float        65536 B
#define K2_MSK 217088                    // 128 float                       512 B
#define K2_TOT 217600

__global__ __launch_bounds__(256, 1) void k2_main(const float* __restrict__ mb2,
                                                  const float* __restrict__ mask) {
    extern __shared__ char sm[];
    __half* sS  = (__half*)(sm + K2_S);
    __half* wT  = (__half*)(sm + K2_W);
    __half* xiS = (__half*)(sm + K2_X);
    float*  part = (float*)(sm + K2_P);
    float*  mskJ = (float*)(sm + K2_MSK);

    int tid = threadIdx.x;
    int b     = blockIdx.x >> 2;
    int ibase = (blockIdx.x & 3) << 5;

    for (int idx = tid; idx < 4096; idx += 256) {
        int r = idx >> 5, c = idx & 31;
        cp16(&sS[r * ST_ + c * 8], &g_S[((size_t)(b * N_ + r)) * H_ + c * 8]);
        cp16(&wT[r * ST_ + c * 8], &g_WT[(size_t)r * H_ + c * 8]);
    }
    for (int idx = tid; idx < 1024; idx += 256)
        cp16(&xiS[idx * 8], &g_XI[((size_t)(b * N_ + ibase)) * H_ + idx * 8]);
    if (tid < 32) cp16(&mskJ[tid * 4], &mask[b * N_ + tid * 4]);
    cp_commit();
    cp_wait<0>();
    __syncthreads();

    int lane = tid & 31, w = tid >> 5;
    int mw = w & 1, jg = w >> 1;

    uint32_t aB = smem_u32(&wT[(mw * 64 + (lane & 15)) * ST_ + ((lane >> 4) & 1) * 8]);
    uint32_t bB = smem_u32(&sS[(jg * 32 + (lane & 15)) * ST_ + ((lane >> 4) & 1) * 8]);

    float bias[4][2];
#pragma unroll
    for (int mt = 0; mt < 4; mt++) {
        bias[mt][0] = mb2[mw * 64 + mt * 16 + (lane >> 2)];
        bias[mt][1] = mb2[mw * 64 + mt * 16 + (lane >> 2) + 8];
    }
    float2 mj[4];
#pragma unroll
    for (int nt = 0; nt < 4; nt++) {
        int j = jg * 32 + nt * 8 + (lane & 3) * 2;
        mj[nt].x = mskJ[j]; mj[nt].y = mskJ[j + 1];
    }

    const __half2 z2 = __float2half2_rn(0.f);

    for (int ip = 0; ip < 16; ip++) {
        int i0 = ip * 2;
        float C[2][4][4][4] = {};          // [il][mt][nt][4]

#pragma unroll 4
        for (int kt = 0; kt < 16; kt++) {
            uint32_t A[4][4];
#pragma unroll
            for (int mt = 0; mt < 4; mt++)
                ldsm_x4(A[mt], aB + mt * (16 * ST_ * 2) + kt * 32);
            uint32_t sf[2][4];
            ldsm_x4(sf[0], bB + kt * 32);
            ldsm_x4(sf[1], bB + 16 * ST_ * 2 + kt * 32);
#pragma unroll
            for (int il = 0; il < 2; il++) {
                __half2 xA = *(const __half2*)&xiS[(i0 + il) * 256 + kt * 16 + (lane & 3) * 2];
                __half2 xB = *(const __half2*)&xiS[(i0 + il) * 256 + kt * 16 + (lane & 3) * 2 + 8];
                uint32_t bf[2][4];
#pragma unroll
                for (int g = 0; g < 2; g++) {
                    __half2 t;
                    t = __hmax2(__hadd2(*(__half2*)&sf[g][0], xA), z2); bf[g][0] = *(uint32_t*)&t;
                    t = __hmax2(__hadd2(*(__half2*)&sf[g][1], xA), z2); bf[g][1] = *(uint32_t*)&t;
                    t = __hmax2(__hadd2(*(__half2*)&sf[g][2], xB), z2); bf[g][2] = *(uint32_t*)&t;
                    t = __hmax2(__hadd2(*(__half2*)&sf[g][3], xB), z2); bf[g][3] = *(uint32_t*)&t;
                }
#pragma unroll
                for (int mt = 0; mt < 4; mt++) {
                    mma16816(C[il][mt][0], A[mt], bf[0][0], bf[0][2]);
                    mma16816(C[il][mt][1], A[mt], bf[0][1], bf[0][3]);
                    mma16816(C[il][mt][2], A[mt], bf[1][0], bf[1][2]);
                    mma16816(C[il][mt][3], A[mt], bf[1][1], bf[1][3]);
                }
            }
        }

        // epilogue: thread-local j reduction, quad shfl, store partials
#pragma unroll
        for (int il = 0; il < 2; il++) {
            int i = i0 + il;
#pragma unroll
            for (int mt = 0; mt < 4; mt++) {
                float s0 = 0.f, s1 = 0.f;
#pragma unroll
                for (int nt = 0; nt < 4; nt++) {
                    s0 += fmaxf(C[il][mt][nt][0] + bias[mt][0], 0.f) * mj[nt].x
                        + fmaxf(C[il][mt][nt][1] + bias[mt][0], 0.f) * mj[nt].y;
                    s1 += fmaxf(C[il][mt][nt][2] + bias[mt][1], 0.f) * mj[nt].x
                        + fmaxf(C[il][mt][nt][3] + bias[mt][1], 0.f) * mj[nt].y;
                }
#pragma unroll
                for (int o = 1; o < 4; o <<= 1) {
                    s0 += __shfl_xor_sync(0xffffffffu, s0, o);
                    s1 += __shfl_xor_sync(0xffffffffu, s1, o);
                }
                if ((lane & 3) == 0) {
                    int d = mw * 64 + mt * 16 + (lane >> 2);
                    part[(jg * 32 + i) * 128 + d]     = s0;
                    part[(jg * 32 + i) * 128 + d + 8] = s1;
                }
            }
        }
    }
    __syncthreads();
    for (int idx = tid; idx < 2048; idx += 256) {
        int i = idx >> 6, dp = (idx & 63) * 2;
        float v0 = part[i * 128 + dp]     + part[(32 + i) * 128 + dp]
                 + part[(64 + i) * 128 + dp]     + part[(96 + i) * 128 + dp];
        float v1 = part[i * 128 + dp + 1] + part[(32 + i) * 128 + dp + 1]
                 + part[(64 + i) * 128 + dp + 1] + part[(96 + i) * 128 + dp + 1];
        *(__half2*)&g_AGGH[((size_t)(b * N_ + ibase + i)) * D_ + dp] = __floats2half2_rn(v0, v1);
    }
}

// ---------------- K3: update MLP + residual + mask (tensor cores, pipelined weights) ----------------
#define K3_A   0                          // 32 x 264 half
#define K3_U   16896                      // 32 x 264 half
#define K3_B1  33792                      // 256 x 264 half (U1T; later U2T rows 64-127)
#define K3_B2  168960                     // 64 x 264 half  (U2T rows 0-63)
#define K3_TOT 202752
__global__ __launch_bounds__(256) void k3_final(
    const float* __restrict__ nodes, const float* __restrict__ mask,
    const float* __restrict__ ub1, const float* __restrict__ ub2,
    float* __restrict__ out) {
    extern __shared__ char sm3[];
    __half* sA = (__half*)(sm3 + K3_A);
    __half* sU = (__half*)(sm3 + K3_U);
    __half* sB1 = (__half*)(sm3 + K3_B1);
    __half* sB2 = (__half*)(sm3 + K3_B2);
    int tid = threadIdx.x;
    int r0 = blockIdx.x * 32;

    // group A: activations + U1T
    for (int idx = tid; idx < 1024; idx += 256) {
        int r = idx >> 5, c = idx & 31;
        const __half* src = (c < 16) ? &g_NH[((size_t)(r0 + r)) * D_ + c * 8]
                                     : &g_AGGH[((size_t)(r0 + r)) * D_ + (c - 16) * 8];
        cp16(&sA[r * ST_ + c * 8], src);
    }
    for (int idx = tid; idx < 8192; idx += 256) {
        int r = idx >> 5, c = idx & 31;
        cp16(&sB1[r * ST_ + c * 8], &g_U1T[r * 256 + c * 8]);
    }
    cp_commit();
    // group B: U2T rows 0-63 (used by warps nq 0,1 in stage 2)
    for (int idx = tid; idx < 2048; idx += 256) {
        int r = idx >> 5, c = idx & 31;
        cp16(&sB2[r * ST_ + c * 8], &g_U2T[r * 256 + c * 8]);
    }
    cp_commit();
    cp_wait<1>();            // group A complete
    __syncthreads();

    int lane = tid & 31, w = tid >> 5;
    int mg = w >> 2, nq = w & 3;

    // ---- stage 1: u = relu([nodes|agg] @ uw1 + ub1) ----
    {
        int n0 = nq * 64;
        uint32_t aB = smem_u32(&sA[(mg * 16 + (lane & 15)) * ST_ + ((lane >> 4) & 1) * 8]);
        uint32_t bB = smem_u32(&sB1[(n0 + (lane & 15)) * ST_ + ((lane >> 4) & 1) * 8]);
        float C[8][4] = {};
#pragma unroll
        for (int kt = 0; kt < 16; kt++) {
            uint32_t am[4], bf[4][4];
            ldsm_x4(am, aB + kt * 32);
#pragma unroll
            for (int q = 0; q < 4; q++) ldsm_x4(bf[q], bB + q * (16 * ST_ * 2) + kt * 32);
#pragma unroll
            for (int q = 0; q < 4; q++) {
                mma16816(C[q * 2],     am, bf[q][0], bf[q][2]);
                mma16816(C[q * 2 + 1], am, bf[q][1], bf[q][3]);
            }
        }
#pragma unroll
        for (int q = 0; q < 4; q++) {
#pragma unroll
            for (int sub = 0; sub < 2; sub++) {
                int nt = q * 2 + sub;
                int col = n0 + q * 16 + sub * 8 + (lane & 3) * 2;
                float b0 = ub1[col], b1 = ub1[col + 1];
                int rowl = mg * 16 + (lane >> 2);
                *(__half2*)&sU[rowl * ST_ + col] =
                    __floats2half2_rn(fmaxf(C[nt][0] + b0, 0.f), fmaxf(C[nt][1] + b1, 0.f));
                *(__half2*)&sU[(rowl + 8) * ST_ + col] =
                    __floats2half2_rn(fmaxf(C[nt][2] + b0, 0.f), fmaxf(C[nt][3] + b1, 0.f));
            }
        }
    }
    __syncthreads();
    // U2T rows 64-127 over the (now dead) U1T region
    for (int idx = tid; idx < 2048; idx += 256) {
        int r = idx >> 5, c = idx & 31;
        cp16(&sB1[r * ST_ + c * 8], &g_U2T[(r + 64) * 256 + c * 8]);
    }
    cp_commit();
    cp_wait<0>();
    __syncthreads();

    // ---- stage 2: out = (nodes + u @ uw2 + ub2) * mask ----
    {
        int n0 = nq * 32;
        const __half* Bst2 = (nq < 2) ? sB2 : sB1;
        int rloc = (nq < 2) ? n0 : (n0 - 64);
        uint32_t aB = smem_u32(&sU[(mg * 16 + (lane & 15)) * ST_ + ((lane >> 4) & 1) * 8]);
        uint32_t bB = smem_u32(&Bst2[(rloc + (lane & 15)) * ST_ + ((lane >> 4) & 1) * 8]);
        float C[4][4] = {};
#pragma unroll
        for (int kt = 0; kt < 16; kt++) {
            uint32_t am[4], bf[2][4];
            ldsm_x4(am, aB + kt * 32);
#pragma unroll
            for (int q = 0; q < 2; q++) ldsm_x4(bf[q], bB + q * (16 * ST_ * 2) + kt * 32);
#pragma unroll
            for (int q = 0; q < 2; q++) {
                mma16816(C[q * 2],     am, bf[q][0], bf[q][2]);
                mma16816(C[q * 2 + 1], am, bf[q][1], bf[q][3]);
            }
        }
        int rowA = r0 + mg * 16 + (lane >> 2);
        float mk0 = mask[rowA], mk1 = mask[rowA + 8];
#pragma unroll
        for (int q = 0; q < 2; q++) {
#pragma unroll
            for (int sub = 0; sub < 2; sub++) {
                int nt = q * 2 + sub;
                int col = n0 + q * 16 + sub * 8 + (lane & 3) * 2;
                float b0 = ub2[col], b1 = ub2[col + 1];
                const float2 nv0 = *(const float2*)&nodes[(size_t)rowA * D_ + col];
                const float2 nv1 = *(const float2*)&nodes[(size_t)(rowA + 8) * D_ + col];
                float2 o0, o1;
                o0.x = (nv0.x + C[nt][0] + b0) * mk0;
                o0.y = (nv0.y + C[nt][1] + b1) * mk0;
                o1.x = (nv1.x + C[nt][2] + b0) * mk1;
                o1.y = (nv1.y + C[nt][3] + b1) * mk1;
                *(float2*)&out[(size_t)rowA * D_ + col]       = o0;
                *(float2*)&out[(size_t)(rowA + 8) * D_ + col] = o1;
            }
        }
    }
}

// ---------------- launch ----------------
extern "C" void kernel_launch(void* const* d_in, const int* in_sizes, int n_in,
                              void* d_out, int out_size) {
    const float* nodes = (const float*)d_in[0];
    const float* mask  = (const float*)d_in[1];
    const float* ln_g  = (const float*)d_in[2];
    const float* ln_b  = (const float*)d_in[3];
    const float* mw1   = (const float*)d_in[4];
    const float* mb1   = (const float*)d_in[5];
    const float* mw2   = (const float*)d_in[6];
    const float* mb2   = (const float*)d_in[7];
    const float* uw1   = (const float*)d_in[8];
    const float* ub1   = (const float*)d_in[9];
    const float* uw2   = (const float*)d_in[10];
    const float* ub2   = (const float*)d_in[11];
    float* out = (float*)d_out;

    cudaFuncSetAttribute(k1_proj,  cudaFuncAttributeMaxDynamicSharedMemorySize, K1_TOT);
    cudaFuncSetAttribute(k2_main,  cudaFuncAttributeMaxDynamicSharedMemorySize, K2_TOT);
    cudaFuncSetAttribute(k3_final, cudaFuncAttributeMaxDynamicSharedMemorySize, K3_TOT);

    kw<<<704, 256>>>(nodes, mw1, mw2, uw1, uw2);
    k1_proj<<<128, 256, K1_TOT>>>(nodes, mask, ln_g, ln_b, mb1);
    k2_main<<<128, 256, K2_TOT>>>(mb2, mask);
    k3_final<<<128, 256, K3_TOT>>>(nodes, mask, ub1, ub2, out);
}

// round 7
// speedup vs baseline: 2.3703x; 1.0519x over previous
#include <cuda_runtime.h>
#include <cuda_fp16.h>
#include <cstdint>

#define B_ 32
#define N_ 128
#define D_ 128
#define H_ 256
#define ROWS_ (B_ * N_)       // 4096
#define ST_ 264               // stride (halves) for K=256 tiles: 528B, mod128=16 -> conflict-free ldsm
#define ST1 136               // stride (halves) for K=128 tiles
#define NSM_ 148

// ---------------- scratch (device globals; no allocation allowed) ----------------
__device__ __half g_XI[ROWS_ * H_];      // receiver projection x@mw1[:D]
__device__ __half g_S [ROWS_ * H_];      // sender projection x@mw1[D:] + mb1
__device__ __half g_WT [D_ * H_];        // mw2^T: [d][h]
__device__ __half g_W1Ta[H_ * D_];       // mw1[:D]^T:  [h][k]
__device__ __half g_W1Tb[H_ * D_];       // mw1[D:]^T:  [h][k]
__device__ __half g_U1T[H_ * 2 * D_];    // uw1^T: [h][k] k=256
__device__ __half g_U2T[D_ * H_];        // uw2^T: [d][k] k=256
__device__ __half g_NH [ROWS_ * D_];     // nodes fp16
__device__ __half g_AGGH[ROWS_ * D_];    // aggregated messages fp16

// ---------------- helpers ----------------
__device__ __forceinline__ uint32_t smem_u32(const void* p) {
    return (uint32_t)__cvta_generic_to_shared(p);
}
__device__ __forceinline__ void cp16(void* s, const void* g) {
    asm volatile("cp.async.cg.shared.global [%0], [%1], 16;" :: "r"(smem_u32(s)), "l"(g));
}
__device__ __forceinline__ void cp_commit() {
    asm volatile("cp.async.commit_group;" ::: "memory");
}
template <int N>
__device__ __forceinline__ void cp_wait() {
    asm volatile("cp.async.wait_group %0;" :: "n"(N) : "memory");
}
__device__ __forceinline__ void ldsm_x4(uint32_t r[4], uint32_t addr) {
    asm volatile("ldmatrix.sync.aligned.m8n8.x4.shared.b16 {%0,%1,%2,%3}, [%4];"
                 : "=r"(r[0]), "=r"(r[1]), "=r"(r[2]), "=r"(r[3]) : "r"(addr));
}
__device__ __forceinline__ void mma16816(float c[4], const uint32_t a[4], uint32_t b0, uint32_t b1) {
    asm volatile("mma.sync.aligned.m16n8k16.row.col.f32.f16.f16.f32 "
                 "{%0,%1,%2,%3}, {%4,%5,%6,%7}, {%8,%9}, {%0,%1,%2,%3};"
                 : "+f"(c[0]), "+f"(c[1]), "+f"(c[2]), "+f"(c[3])
                 : "r"(a[0]), "r"(a[1]), "r"(a[2]), "r"(a[3]), "r"(b0), "r"(b1));
}

// ---------------- KW: coalesced tiled transposes + nodes->fp16 ----------------
__global__ void kw(const float* __restrict__ nodes, const float* __restrict__ mw1,
                   const float* __restrict__ mw2, const float* __restrict__ uw1,
                   const float* __restrict__ uw2) {
    __shared__ float tile[32][33];
    int bid = blockIdx.x, tid = threadIdx.x;
    if (bid < 512) {           // nodes -> fp16, coalesced
        int idx = bid * 1024 + tid * 4;
        float4 v = *(const float4*)&nodes[idx];
        __half2* o = (__half2*)&g_NH[idx];
        o[0] = __floats2half2_rn(v.x, v.y);
        o[1] = __floats2half2_rn(v.z, v.w);
        return;
    }
    int t = bid - 512;
    const float* src; __half* dst; int srcLd, dstLd, tr, tc;
    if (t < 32)       { src = mw1;            dst = g_W1Ta; srcLd = 256; dstLd = 128; tr = t >> 3;  tc = t & 7; }
    else if (t < 64)  { t -= 32; src = mw1 + 128 * 256; dst = g_W1Tb; srcLd = 256; dstLd = 128; tr = t >> 3; tc = t & 7; }
    else if (t < 96)  { t -= 64; src = mw2;   dst = g_WT;   srcLd = 128; dstLd = 256; tr = t >> 2;  tc = t & 3; }
    else if (t < 160) { t -= 96; src = uw1;   dst = g_U1T;  srcLd = 256; dstLd = 256; tr = t >> 3;  tc = t & 7; }
    else              { t -= 160; src = uw2;  dst = g_U2T;  srcLd = 128; dstLd = 256; tr = t >> 2;  tc = t & 3; }
    int r0 = tr * 32, c0 = tc * 32;
    int lr = tid >> 3, lc = (tid & 7) * 4;
    float4 v = *(const float4*)&src[(size_t)(r0 + lr) * srcLd + c0 + lc];
    tile[lr][lc] = v.x; tile[lr][lc + 1] = v.y; tile[lr][lc + 2] = v.z; tile[lr][lc + 3] = v.w;
    __syncthreads();
    __half2 p0 = __floats2half2_rn(tile[lc][lr],     tile[lc + 1][lr]);
    __half2 p1 = __floats2half2_rn(tile[lc + 2][lr], tile[lc + 3][lr]);
    __half2* o = (__half2*)&dst[(size_t)(c0 + lr) * dstLd + r0 + lc];
    o[0] = p0; o[1] = p1;
}

// ---------------- K1: fused LayerNorm + mma projections ----------------
#define K1_XH 0
#define K1_BA 8704
#define K1_BB 78336
#define K1_TOT 147968
__global__ __launch_bounds__(256) void k1_proj(const float* __restrict__ nodes,
                                               const float* __restrict__ mask,
                                               const float* __restrict__ gam,
                                               const float* __restrict__ bet,
                                               const float* __restrict__ mb1) {
    extern __shared__ char sm1[];
    __half* xh = (__half*)(sm1 + K1_XH);
    __half* Ba = (__half*)(sm1 + K1_BA);
    __half* Bb = (__half*)(sm1 + K1_BB);
    int tid = threadIdx.x;
    int r0 = blockIdx.x * 32;

    for (int idx = tid; idx < 4096; idx += 256) {
        int r = idx >> 4, c = idx & 15;
        cp16(&Ba[r * ST1 + c * 8], &g_W1Ta[r * 128 + c * 8]);
        cp16(&Bb[r * ST1 + c * 8], &g_W1Tb[r * 128 + c * 8]);
    }
    cp_commit();

    {   // fused LayerNorm * mask -> xh (fp16)
        int row = tid >> 3, p = tid & 7;
        const float* np = &nodes[(size_t)(r0 + row) * D_ + p * 16];
        float4 v[4];
#pragma unroll
        for (int q = 0; q < 4; q++) v[q] = *(const float4*)&np[q * 4];
        float s = 0.f, s2 = 0.f;
#pragma unroll
        for (int q = 0; q < 4; q++) {
            s  += v[q].x + v[q].y + v[q].z + v[q].w;
            s2 += v[q].x*v[q].x + v[q].y*v[q].y + v[q].z*v[q].z + v[q].w*v[q].w;
        }
#pragma unroll
        for (int o = 1; o < 8; o <<= 1) {
            s  += __shfl_xor_sync(0xffffffffu, s,  o);
            s2 += __shfl_xor_sync(0xffffffffu, s2, o);
        }
        float mu  = s * (1.0f / 128.0f);
        float var = s2 * (1.0f / 128.0f) - mu * mu;
        float rs  = rsqrtf(var + 1e-5f);
        float m   = mask[r0 + row];
        __half* xo = &xh[row * ST1 + p * 16];
        const float* gp = &gam[p * 16];
        const float* bp = &bet[p * 16];
        const float* vv = (const float*)v;
#pragma unroll
        for (int q = 0; q < 16; q++)
            xo[q] = __float2half(((vv[q] - mu) * rs * gp[q] + bp[q]) * m);
    }
    cp_wait<0>();
    __syncthreads();

    int lane = tid & 31, w = tid >> 5;
    int isS = w >> 2, nq = w & 3, n0 = nq * 64;
    const __half* Bsel = isS ? Bb : Ba;
    uint32_t aB = smem_u32(&xh[(lane & 15) * ST1 + ((lane >> 4) & 1) * 8]);
    uint32_t bB = smem_u32(&Bsel[(n0 + (lane & 15)) * ST1 + ((lane >> 4) & 1) * 8]);

    float C[2][8][4] = {};
#pragma unroll
    for (int kt = 0; kt < 8; kt++) {
        uint32_t am[2][4], bf[4][4];
#pragma unroll
        for (int mt = 0; mt < 2; mt++) ldsm_x4(am[mt], aB + mt * (16 * ST1 * 2) + kt * 32);
#pragma unroll
        for (int q = 0; q < 4; q++) ldsm_x4(bf[q], bB + q * (16 * ST1 * 2) + kt * 32);
#pragma unroll
        for (int mt = 0; mt < 2; mt++)
#pragma unroll
            for (int q = 0; q < 4; q++) {
                mma16816(C[mt][q * 2],     am[mt], bf[q][0], bf[q][2]);
                mma16816(C[mt][q * 2 + 1], am[mt], bf[q][1], bf[q][3]);
            }
    }

    __half* dst = isS ? g_S : g_XI;
#pragma unroll
    for (int mt = 0; mt < 2; mt++) {
#pragma unroll
        for (int q = 0; q < 4; q++) {
#pragma unroll
            for (int sub = 0; sub < 2; sub++) {
                int nt = q * 2 + sub;
                int col = n0 + q * 16 + sub * 8 + (lane & 3) * 2;
                float b0 = 0.f, b1 = 0.f;
                if (isS) { b0 = mb1[col]; b1 = mb1[col + 1]; }
                int rowA = r0 + mt * 16 + (lane >> 2);
                *(__half2*)&dst[(size_t)rowA * H_ + col] =
                    __floats2half2_rn(C[mt][nt][0] + b0, C[mt][nt][1] + b1);
                *(__half2*)&dst[(size_t)(rowA + 8) * H_ + col] =
                    __floats2half2_rn(C[mt][nt][2] + b0, C[mt][nt][3] + b1);
            }
        }
    }
}

// ---------------- K2: persistent grid-148, units of 4 i's, pipelined kt loop ----------------
// unit u in [0,1024): b = u>>5, i-quad ic = u&31 (i = ic*4 .. ic*4+3).
// block bx handles units [bx*1024/148, (bx+1)*1024/148) -> <=7 units, <=2 distinct b.
// warps: mw = wid&1 -> d rows [mw*64..+64); jg = wid>>1 -> j in [jg*32..+32).
#define K2_W   0                          // 128 x 264 half (WT)          67584 B
#define K2_S   67584                      // 128 x 264 half (S rows)      67584 B
#define K2_X   135168                     // 4 x 256 half (xi quad)        2048 B
#define K2_P   137216                     // part[16][128] float           8192 B
#define K2_MSK 145408                     // 128 float                      512 B
#define K2_TOT 145920

__global__ __launch_bounds__(256, 1) void k2_main(const float* __restrict__ mb2,
                                                  const float* __restrict__ mask) {
    extern __shared__ char sm[];
    __half* wT  = (__half*)(sm + K2_W);
    __half* sS  = (__half*)(sm + K2_S);
    __half* xiS = (__half*)(sm + K2_X);
    float*  part = (float*)(sm + K2_P);
    float*  mskJ = (float*)(sm + K2_MSK);

    int tid = threadIdx.x;
    int u0 = (blockIdx.x * 1024) / NSM_;
    int u1 = ((blockIdx.x + 1) * 1024) / NSM_;

    // WT load (own group)
    for (int idx = tid; idx < 4096; idx += 256) {
        int r = idx >> 5, c = idx & 31;
        cp16(&wT[r * ST_ + c * 8], &g_WT[(size_t)r * H_ + c * 8]);
    }
    cp_commit();

    int lane = tid & 31, w = tid >> 5;
    int mw = w & 1, jg = w >> 1;

    uint32_t aB = smem_u32(&wT[(mw * 64 + (lane & 15)) * ST_ + ((lane >> 4) & 1) * 8]);
    uint32_t bB = smem_u32(&sS[(jg * 32 + (lane & 15)) * ST_ + ((lane >> 4) & 1) * 8]);

    float bias[4][2];
#pragma unroll
    for (int mt = 0; mt < 4; mt++) {
        bias[mt][0] = mb2[mw * 64 + mt * 16 + (lane >> 2)];
        bias[mt][1] = mb2[mw * 64 + mt * 16 + (lane >> 2) + 8];
    }

    const __half2 z2 = __float2half2_rn(0.f);
    int curb = -1;
    float2 mj[4];

    for (int u = u0; u < u1; u++) {
        int b = u >> 5, ic = u & 31;
        if (b != curb) {
            __syncthreads();              // everyone done reading old S
            for (int idx = tid; idx < 4096; idx += 256) {
                int r = idx >> 5, c = idx & 31;
                cp16(&sS[r * ST_ + c * 8], &g_S[((size_t)(b * N_ + r)) * H_ + c * 8]);
            }
            if (tid < 32) cp16(&mskJ[tid * 4], &mask[b * N_ + tid * 4]);
            cp_commit();
            cp_wait<0>();
            __syncthreads();
            curb = b;
#pragma unroll
            for (int nt = 0; nt < 4; nt++) {
                int j = jg * 32 + nt * 8 + (lane & 3) * 2;
                mj[nt].x = mskJ[j]; mj[nt].y = mskJ[j + 1];
            }
        }
        // xi for this i-quad (4 rows x 512B)
        if (tid < 128)
            cp16(&xiS[tid * 8], &g_XI[((size_t)(b * N_ + ic * 4)) * H_ + tid * 8]);
        cp_commit();
        cp_wait<0>();
        __syncthreads();                  // xi ready; prev part consumed

        for (int ip = 0; ip < 2; ip++) {
            int i0 = ip * 2;
            float C[2][4][4][4] = {};      // [il][mt][nt][4]

            // pipelined kt loop: sf/x double-buffered one kt ahead
            uint32_t sf[2][2][4];
            __half2 xA[2][2], xB[2][2];
            ldsm_x4(sf[0][0], bB);
            ldsm_x4(sf[0][1], bB + 16 * ST_ * 2);
#pragma unroll
            for (int il = 0; il < 2; il++) {
                xA[0][il] = *(const __half2*)&xiS[(i0 + il) * 256 + (lane & 3) * 2];
                xB[0][il] = *(const __half2*)&xiS[(i0 + il) * 256 + (lane & 3) * 2 + 8];
            }
#pragma unroll
            for (int kt = 0; kt < 16; kt++) {
                const int cur = kt & 1, nxt = cur ^ 1;
                uint32_t A[4][4];
#pragma unroll
                for (int mt = 0; mt < 4; mt++)
                    ldsm_x4(A[mt], aB + mt * (16 * ST_ * 2) + kt * 32);
                if (kt < 15) {
                    ldsm_x4(sf[nxt][0], bB + (kt + 1) * 32);
                    ldsm_x4(sf[nxt][1], bB + 16 * ST_ * 2 + (kt + 1) * 32);
#pragma unroll
                    for (int il = 0; il < 2; il++) {
                        xA[nxt][il] = *(const __half2*)&xiS[(i0 + il) * 256 + (kt + 1) * 16 + (lane & 3) * 2];
                        xB[nxt][il] = *(const __half2*)&xiS[(i0 + il) * 256 + (kt + 1) * 16 + (lane & 3) * 2 + 8];
                    }
                }
#pragma unroll
                for (int il = 0; il < 2; il++) {
                    uint32_t bf[2][4];
#pragma unroll
                    for (int g = 0; g < 2; g++) {
                        __half2 t;
                        t = __hmax2(__hadd2(*(__half2*)&sf[cur][g][0], xA[cur][il]), z2); bf[g][0] = *(uint32_t*)&t;
                        t = __hmax2(__hadd2(*(__half2*)&sf[cur][g][1], xA[cur][il]), z2); bf[g][1] = *(uint32_t*)&t;
                        t = __hmax2(__hadd2(*(__half2*)&sf[cur][g][2], xB[cur][il]), z2); bf[g][2] = *(uint32_t*)&t;
                        t = __hmax2(__hadd2(*(__half2*)&sf[cur][g][3], xB[cur][il]), z2); bf[g][3] = *(uint32_t*)&t;
                    }
#pragma unroll
                    for (int mt = 0; mt < 4; mt++) {
                        mma16816(C[il][mt][0], A[mt], bf[0][0], bf[0][2]);
                        mma16816(C[il][mt][1], A[mt], bf[0][1], bf[0][3]);
                        mma16816(C[il][mt][2], A[mt], bf[1][0], bf[1][2]);
                        mma16816(C[il][mt][3], A[mt], bf[1][1], bf[1][3]);
                    }
                }
            }

            // epilogue: thread-local j reduction, quad shfl, store partials
#pragma unroll
            for (int il = 0; il < 2; il++) {
#pragma unroll
                for (int mt = 0; mt < 4; mt++) {
                    float s0 = 0.f, s1 = 0.f;
#pragma unroll
                    for (int nt = 0; nt < 4; nt++) {
                        s0 += fmaxf(C[il][mt][nt][0] + bias[mt][0], 0.f) * mj[nt].x
                            + fmaxf(C[il][mt][nt][1] + bias[mt][0], 0.f) * mj[nt].y;
                        s1 += fmaxf(C[il][mt][nt][2] + bias[mt][1], 0.f) * mj[nt].x
                            + fmaxf(C[il][mt][nt][3] + bias[mt][1], 0.f) * mj[nt].y;
                    }
#pragma unroll
                    for (int o = 1; o < 4; o <<= 1) {
                        s0 += __shfl_xor_sync(0xffffffffu, s0, o);
                        s1 += __shfl_xor_sync(0xffffffffu, s1, o);
                    }
                    if ((lane & 3) == 0) {
                        int d = mw * 64 + mt * 16 + (lane >> 2);
                        part[(jg * 4 + i0 + il) * 128 + d]     = s0;
                        part[(jg * 4 + i0 + il) * 128 + d + 8] = s1;
                    }
                }
            }
        }
        __syncthreads();                  // all partials written
        {
            int i4 = tid >> 6, dp = (tid & 63) * 2;
            float v0 = part[i4 * 128 + dp]     + part[(4 + i4) * 128 + dp]
                     + part[(8 + i4) * 128 + dp]     + part[(12 + i4) * 128 + dp];
            float v1 = part[i4 * 128 + dp + 1] + part[(4 + i4) * 128 + dp + 1]
                     + part[(8 + i4) * 128 + dp + 1] + part[(12 + i4) * 128 + dp + 1];
            *(__half2*)&g_AGGH[((size_t)(b * N_ + ic * 4 + i4)) * D_ + dp] =
                __floats2half2_rn(v0, v1);
        }
    }
}

// ---------------- K3: update MLP + residual + mask (tensor cores, pipelined weights) ----------------
#define K3_A   0                          // 32 x 264 half
#define K3_U   16896                      // 32 x 264 half
#define K3_B1  33792                      // 256 x 264 half (U1T; later U2T rows 64-127)
#define K3_B2  168960                     // 64 x 264 half  (U2T rows 0-63)
#define K3_TOT 202752
__global__ __launch_bounds__(256) void k3_final(
    const float* __restrict__ nodes, const float* __restrict__ mask,
    const float* __restrict__ ub1, const float* __restrict__ ub2,
    float* __restrict__ out) {
    extern __shared__ char sm3[];
    __half* sA = (__half*)(sm3 + K3_A);
    __half* sU = (__half*)(sm3 + K3_U);
    __half* sB1 = (__half*)(sm3 + K3_B1);
    __half* sB2 = (__half*)(sm3 + K3_B2);
    int tid = threadIdx.x;
    int r0 = blockIdx.x * 32;

    for (int idx = tid; idx < 1024; idx += 256) {
        int r = idx >> 5, c = idx & 31;
        const __half* src = (c < 16) ? &g_NH[((size_t)(r0 + r)) * D_ + c * 8]
                                     : &g_AGGH[((size_t)(r0 + r)) * D_ + (c - 16) * 8];
        cp16(&sA[r * ST_ + c * 8], src);
    }
    for (int idx = tid; idx < 8192; idx += 256) {
        int r = idx >> 5, c = idx & 31;
        cp16(&sB1[r * ST_ + c * 8], &g_U1T[r * 256 + c * 8]);
    }
    cp_commit();
    for (int idx = tid; idx < 2048; idx += 256) {
        int r = idx >> 5, c = idx & 31;
        cp16(&sB2[r * ST_ + c * 8], &g_U2T[r * 256 + c * 8]);
    }
    cp_commit();
    cp_wait<1>();
    __syncthreads();

    int lane = tid & 31, w = tid >> 5;
    int mg = w >> 2, nq = w & 3;

    // ---- stage 1: u = relu([nodes|agg] @ uw1 + ub1) ----
    {
        int n0 = nq * 64;
        uint32_t aB = smem_u32(&sA[(mg * 16 + (lane & 15)) * ST_ + ((lane >> 4) & 1) * 8]);
        uint32_t bB = smem_u32(&sB1[(n0 + (lane & 15)) * ST_ + ((lane >> 4) & 1) * 8]);
        float C[8][4] = {};
#pragma unroll
        for (int kt = 0; kt < 16; kt++) {
            uint32_t am[4], bf[4][4];
            ldsm_x4(am, aB + kt * 32);
#pragma unroll
            for (int q = 0; q < 4; q++) ldsm_x4(bf[q], bB + q * (16 * ST_ * 2) + kt * 32);
#pragma unroll
            for (int q = 0; q < 4; q++) {
                mma16816(C[q * 2],     am, bf[q][0], bf[q][2]);
                mma16816(C[q * 2 + 1], am, bf[q][1], bf[q][3]);
            }
        }
#pragma unroll
        for (int q = 0; q < 4; q++) {
#pragma unroll
            for (int sub = 0; sub < 2; sub++) {
                int nt = q * 2 + sub;
                int col = n0 + q * 16 + sub * 8 + (lane & 3) * 2;
                float b0 = ub1[col], b1 = ub1[col + 1];
                int rowl = mg * 16 + (lane >> 2);
                *(__half2*)&sU[rowl * ST_ + col] =
                    __floats2half2_rn(fmaxf(C[nt][0] + b0, 0.f), fmaxf(C[nt][1] + b1, 0.f));
                *(__half2*)&sU[(rowl + 8) * ST_ + col] =
                    __floats2half2_rn(fmaxf(C[nt][2] + b0, 0.f), fmaxf(C[nt][3] + b1, 0.f));
            }
        }
    }
    __syncthreads();
    for (int idx = tid; idx < 2048; idx += 256) {
        int r = idx >> 5, c = idx & 31;
        cp16(&sB1[r * ST_ + c * 8], &g_U2T[(r + 64) * 256 + c * 8]);
    }
    cp_commit();
    cp_wait<0>();
    __syncthreads();

    // ---- stage 2: out = (nodes + u @ uw2 + ub2) * mask ----
    {
        int n0 = nq * 32;
        const __half* Bst2 = (nq < 2) ? sB2 : sB1;
        int rloc = (nq < 2) ? n0 : (n0 - 64);
        uint32_t aB = smem_u32(&sU[(mg * 16 + (lane & 15)) * ST_ + ((lane >> 4) & 1) * 8]);
        uint32_t bB = smem_u32(&Bst2[(rloc + (lane & 15)) * ST_ + ((lane >> 4) & 1) * 8]);
        float C[4][4] = {};
#pragma unroll
        for (int kt = 0; kt < 16; kt++) {
            uint32_t am[4], bf[2][4];
            ldsm_x4(am, aB + kt * 32);
#pragma unroll
            for (int q = 0; q < 2; q++) ldsm_x4(bf[q], bB + q * (16 * ST_ * 2) + kt * 32);
#pragma unroll
            for (int q = 0; q < 2; q++) {
                mma16816(C[q * 2],     am, bf[q][0], bf[q][2]);
                mma16816(C[q * 2 + 1], am, bf[q][1], bf[q][3]);
            }
        }
        int rowA = r0 + mg * 16 + (lane >> 2);
        float mk0 = mask[rowA], mk1 = mask[rowA + 8];
#pragma unroll
        for (int q = 0; q < 2; q++) {
#pragma unroll
            for (int sub = 0; sub < 2; sub++) {
                int nt = q * 2 + sub;
                int col = n0 + q * 16 + sub * 8 + (lane & 3) * 2;
                float b0 = ub2[col], b1 = ub2[col + 1];
                const float2 nv0 = *(const float2*)&nodes[(size_t)rowA * D_ + col];
                const float2 nv1 = *(const float2*)&nodes[(size_t)(rowA + 8) * D_ + col];
                float2 o0, o1;
                o0.x = (nv0.x + C[nt][0] + b0) * mk0;
                o0.y = (nv0.y + C[nt][1] + b1) * mk0;
                o1.x = (nv1.x + C[nt][2] + b0) * mk1;
                o1.y = (nv1.y + C[nt][3] + b1) * mk1;
                *(float2*)&out[(size_t)rowA * D_ + col]       = o0;
                *(float2*)&out[(size_t)(rowA + 8) * D_ + col] = o1;
            }
        }
    }
}

// ---------------- launch ----------------
extern "C" void kernel_launch(void* const* d_in, const int* in_sizes, int n_in,
                              void* d_out, int out_size) {
    const float* nodes = (const float*)d_in[0];
    const float* mask  = (const float*)d_in[1];
    const float* ln_g  = (const float*)d_in[2];
    const float* ln_b  = (const float*)d_in[3];
    const float* mw1   = (const float*)d_in[4];
    const float* mb1   = (const float*)d_in[5];
    const float* mw2   = (const float*)d_in[6];
    const float* mb2   = (const float*)d_in[7];
    const float* uw1   = (const float*)d_in[8];
    const float* ub1   = (const float*)d_in[9];
    const float* uw2   = (const float*)d_in[10];
    const float* ub2   = (const float*)d_in[11];
    float* out = (float*)d_out;

    cudaFuncSetAttribute(k1_proj,  cudaFuncAttributeMaxDynamicSharedMemorySize, K1_TOT);
    cudaFuncSetAttribute(k2_main,  cudaFuncAttributeMaxDynamicSharedMemorySize, K2_TOT);
    cudaFuncSetAttribute(k3_final, cudaFuncAttributeMaxDynamicSharedMemorySize, K3_TOT);

    kw<<<704, 256>>>(nodes, mw1, mw2, uw1, uw2);
    k1_proj<<<128, 256, K1_TOT>>>(nodes, mask, ln_g, ln_b, mb1);
    k2_main<<<NSM_, 256, K2_TOT>>>(mb2, mask);
    k3_final<<<128, 256, K3_TOT>>>(nodes, mask, ub1, ub2, out);
}